// round 4
// baseline (speedup 1.0000x reference)
#include <cuda_runtime.h>
#include <math.h>

// Problem constants
#define B   2
#define T   2048
#define E   2048
#define G   4
#define QPG 4
#define D   128
#define NH  (G*QPG)     // 16 heads
#define QDIM (NH*D)     // 2048
#define KVDIM (2*G*D)   // 1024
#define MROWS (B*T)     // 4096

// Scratch (device globals: no allocations allowed)
__device__ float g_q  [MROWS * QDIM];   // q   = x@wq + bq + pe      [B*T, 2048]
__device__ float g_kv [MROWS * KVDIM];  // kv  = x@wkv + bkv (+pe on k half) [B*T, 1024]
__device__ float g_att[MROWS * QDIM];   // attention output          [B*T, 2048]
__device__ float g_pe [T * D];          // sinusoidal PE table

// ---------------------------------------------------------------------------
// PE table init (recomputed every launch — deterministic, trivial cost)
// ---------------------------------------------------------------------------
__global__ void pe_init_kernel() {
    int idx = blockIdx.x * blockDim.x + threadIdx.x;
    if (idx >= T * D) return;
    int t = idx / D, d = idx % D;
    float i2  = (float)(d & ~1);                       // 2*floor(d/2)
    float inv = expf(-(logf(10000.0f) * i2 / (float)D));
    float ang = (float)t * inv;
    g_pe[idx] = (d & 1) ? cosf(ang) : sinf(ang);
}

// ---------------------------------------------------------------------------
// Tiled SGEMM: C[M,N] = A[M,K] @ W[K,N] (+bias) (+PE per mode)
// 128x128 block tile, 8x8 per thread, K-tile 16, 256 threads.
// mode 0: plain      mode 1: +bias +pe (q proj)    mode 2: +bias +pe on k-half (kv proj)
// ---------------------------------------------------------------------------
#define TK 16
__global__ __launch_bounds__(256) void sgemm_kernel(
    const float* __restrict__ A, const float* __restrict__ W,
    const float* __restrict__ bias, float* __restrict__ C,
    int M, int N, int K, int mode)
{
    __shared__ float As[TK][132];   // stored transposed: As[k][m], padded
    __shared__ float Bs[TK][132];   // Bs[k][n], padded

    const int tid = threadIdx.x;
    const int bm = blockIdx.y * 128;
    const int bn = blockIdx.x * 128;

    // A loader: 128 rows x 16 k = 512 float4; 2 per thread
    const int a_row = tid >> 2;            // 0..63 (plus +64)
    const int a_col = (tid & 3) * 4;       // 0,4,8,12
    // B loader: 16 k rows x 128 n = 512 float4; 2 per thread
    const int b_row = tid >> 4;            // 0..15
    const int b_col = (tid & 15) * 8;      // 0..120 (two float4)

    const int tx = tid & 15, ty = tid >> 4;

    float acc[8][8];
    #pragma unroll
    for (int i = 0; i < 8; i++)
        #pragma unroll
        for (int j = 0; j < 8; j++) acc[i][j] = 0.f;

    for (int k0 = 0; k0 < K; k0 += TK) {
        // load A tile (transpose into As[k][m])
        #pragma unroll
        for (int h = 0; h < 2; h++) {
            int r = a_row + h * 64;
            float4 av = *reinterpret_cast<const float4*>(&A[(size_t)(bm + r) * K + k0 + a_col]);
            As[a_col + 0][r] = av.x;
            As[a_col + 1][r] = av.y;
            As[a_col + 2][r] = av.z;
            As[a_col + 3][r] = av.w;
        }
        // load B tile
        {
            const float* wrow = &W[(size_t)(k0 + b_row) * N + bn + b_col];
            float4 b0 = *reinterpret_cast<const float4*>(wrow);
            float4 b1 = *reinterpret_cast<const float4*>(wrow + 4);
            *reinterpret_cast<float4*>(&Bs[b_row][b_col])     = b0;
            *reinterpret_cast<float4*>(&Bs[b_row][b_col + 4]) = b1;
        }
        __syncthreads();

        #pragma unroll
        for (int kk = 0; kk < TK; kk++) {
            float ra[8], rb[8];
            *reinterpret_cast<float4*>(&ra[0]) = *reinterpret_cast<const float4*>(&As[kk][ty * 4]);
            *reinterpret_cast<float4*>(&ra[4]) = *reinterpret_cast<const float4*>(&As[kk][ty * 4 + 64]);
            *reinterpret_cast<float4*>(&rb[0]) = *reinterpret_cast<const float4*>(&Bs[kk][tx * 4]);
            *reinterpret_cast<float4*>(&rb[4]) = *reinterpret_cast<const float4*>(&Bs[kk][tx * 4 + 64]);
            #pragma unroll
            for (int i = 0; i < 8; i++)
                #pragma unroll
                for (int j = 0; j < 8; j++)
                    acc[i][j] = fmaf(ra[i], rb[j], acc[i][j]);
        }
        __syncthreads();
    }

    // epilogue
    #pragma unroll
    for (int i = 0; i < 8; i++) {
        int row = bm + ty * 4 + (i & 3) + (i >> 2) * 64;
        int t   = row & (T - 1);
        #pragma unroll
        for (int j = 0; j < 8; j++) {
            int col = bn + tx * 4 + (j & 3) + (j >> 2) * 64;
            float v = acc[i][j];
            if (mode != 0) v += bias[col];
            if (mode == 1) {
                v += g_pe[t * D + (col & (D - 1))];
            } else if (mode == 2) {
                int dc = col & (2 * D - 1);
                if (dc < D) v += g_pe[t * D + dc];
            }
            C[(size_t)row * N + col] = v;
        }
    }
}

// ---------------------------------------------------------------------------
// Flash attention (causal, online softmax). fp32.
// One CTA: 64 query rows of one head. 256 threads. Loops over 64-key tiles.
// ---------------------------------------------------------------------------
#define BR 64
#define BC 64
#define KP 132   // padded row stride for Q/K/V tiles (conflict-free)
#define SP 65    // padded row stride for score tile

struct FlashSmem {
    float Q [BR][KP];
    float Kt[BC][KP];
    float Vt[BC][KP];
    float S [BR][SP];
    float m[BR];
    float l[BR];
    float scale[BR];
};

__global__ __launch_bounds__(256) void flash_kernel(
    const float* __restrict__ Qg, const float* __restrict__ KVg, float* __restrict__ Og)
{
    extern __shared__ float smem_raw[];
    FlashSmem* sm = reinterpret_cast<FlashSmem*>(smem_raw);

    const int tid  = threadIdx.x;
    const int qb   = blockIdx.x * BR;
    const int head = blockIdx.y;        // g = head>>2, qpg = head&3
    const int b    = blockIdx.z;
    const int g    = head >> 2;

    const float* qbase  = Qg  + (size_t)b * T * QDIM  + head * D;
    const float* kvbase = KVg + (size_t)b * T * KVDIM + g * (2 * D);
    float*       obase  = Og  + (size_t)b * T * QDIM  + head * D;

    // Load Q tile: 64x128, 8 float4 per thread, coalesced
    {
        int r0 = tid >> 5;             // 0..7
        int c  = (tid & 31) * 4;       // 0..124
        #pragma unroll
        for (int i = 0; i < 8; i++) {
            int r = r0 + i * 8;
            *reinterpret_cast<float4*>(&sm->Q[r][c]) =
                *reinterpret_cast<const float4*>(&qbase[(size_t)(qb + r) * QDIM + c]);
        }
    }
    if (tid < BR) { sm->m[tid] = -INFINITY; sm->l[tid] = 0.f; }

    const int tx = tid & 15, ty = tid >> 4;

    float acc[4][8];   // rows ty+16i, cols tx+16c
    #pragma unroll
    for (int i = 0; i < 4; i++)
        #pragma unroll
        for (int c = 0; c < 8; c++) acc[i][c] = 0.f;

    const int ntiles = qb / BC + 1;

    for (int kt = 0; kt < ntiles; kt++) {
        __syncthreads();   // protect Kt/Vt/S from previous iteration consumers
        // Load K,V tiles
        {
            int r0 = tid >> 5;
            int c  = (tid & 31) * 4;
            #pragma unroll
            for (int i = 0; i < 8; i++) {
                int r = r0 + i * 8;
                const float* kvrow = &kvbase[(size_t)(kt * BC + r) * KVDIM];
                *reinterpret_cast<float4*>(&sm->Kt[r][c]) =
                    *reinterpret_cast<const float4*>(&kvrow[c]);
                *reinterpret_cast<float4*>(&sm->Vt[r][c]) =
                    *reinterpret_cast<const float4*>(&kvrow[D + c]);
            }
        }
        __syncthreads();

        // Scores: S[r][c] = (Q[r,:] . K[c,:]) / sqrt(D); r = ty+16i, c = tx+16j
        {
            float racc[4][4];
            #pragma unroll
            for (int i = 0; i < 4; i++)
                #pragma unroll
                for (int j = 0; j < 4; j++) racc[i][j] = 0.f;

            #pragma unroll 4
            for (int k4 = 0; k4 < D; k4 += 4) {
                float4 qa[4], kb[4];
                #pragma unroll
                for (int i = 0; i < 4; i++)
                    qa[i] = *reinterpret_cast<const float4*>(&sm->Q[ty + 16 * i][k4]);
                #pragma unroll
                for (int j = 0; j < 4; j++)
                    kb[j] = *reinterpret_cast<const float4*>(&sm->Kt[tx + 16 * j][k4]);
                #pragma unroll
                for (int i = 0; i < 4; i++)
                    #pragma unroll
                    for (int j = 0; j < 4; j++) {
                        racc[i][j] = fmaf(qa[i].x, kb[j].x, racc[i][j]);
                        racc[i][j] = fmaf(qa[i].y, kb[j].y, racc[i][j]);
                        racc[i][j] = fmaf(qa[i].z, kb[j].z, racc[i][j]);
                        racc[i][j] = fmaf(qa[i].w, kb[j].w, racc[i][j]);
                    }
            }
            const float sc = 0.08838834764831845f;  // 1/sqrt(128)
            #pragma unroll
            for (int i = 0; i < 4; i++)
                #pragma unroll
                for (int j = 0; j < 4; j++)
                    sm->S[ty + 16 * i][tx + 16 * j] = racc[i][j] * sc;
        }
        __syncthreads();

        // Online softmax: thread -> row r = tid>>2, col block (tid&3)*16
        {
            int r     = tid >> 2;
            int part  = tid & 3;
            int row_g = qb + r;
            float vals[16];
            float mx = -INFINITY;
            #pragma unroll
            for (int c = 0; c < 16; c++) {
                int cc = part * 16 + c;
                float s = sm->S[r][cc];
                s = ((kt * BC + cc) <= row_g) ? s : -INFINITY;
                vals[c] = s;
                mx = fmaxf(mx, s);
            }
            mx = fmaxf(mx, __shfl_xor_sync(0xFFFFFFFF, mx, 1));
            mx = fmaxf(mx, __shfl_xor_sync(0xFFFFFFFF, mx, 2));
            float m_old = sm->m[r];
            float m_new = fmaxf(m_old, mx);
            float sum = 0.f;
            #pragma unroll
            for (int c = 0; c < 16; c++) {
                float p = __expf(vals[c] - m_new);
                sm->S[r][part * 16 + c] = p;
                sum += p;
            }
            sum += __shfl_xor_sync(0xFFFFFFFF, sum, 1);
            sum += __shfl_xor_sync(0xFFFFFFFF, sum, 2);
            if (part == 0) {
                float scl = __expf(m_old - m_new);
                sm->scale[r] = scl;
                sm->l[r] = sm->l[r] * scl + sum;
                sm->m[r] = m_new;
            }
        }
        __syncthreads();

        // acc rescale + P@V
        {
            float rs[4];
            #pragma unroll
            for (int i = 0; i < 4; i++) rs[i] = sm->scale[ty + 16 * i];
            #pragma unroll
            for (int i = 0; i < 4; i++)
                #pragma unroll
                for (int c = 0; c < 8; c++) acc[i][c] *= rs[i];

            #pragma unroll 2
            for (int j = 0; j < BC; j++) {
                float p[4];
                #pragma unroll
                for (int i = 0; i < 4; i++) p[i] = sm->S[ty + 16 * i][j];
                float vv[8];
                #pragma unroll
                for (int c = 0; c < 8; c++) vv[c] = sm->Vt[j][tx + 16 * c];
                #pragma unroll
                for (int i = 0; i < 4; i++)
                    #pragma unroll
                    for (int c = 0; c < 8; c++)
                        acc[i][c] = fmaf(p[i], vv[c], acc[i][c]);
            }
        }
    }
    __syncthreads();

    // Finalize: divide by l, write out
    {
        float rl[4];
        #pragma unroll
        for (int i = 0; i < 4; i++) rl[i] = 1.f / sm->l[ty + 16 * i];
        #pragma unroll
        for (int i = 0; i < 4; i++) {
            int r = qb + ty + 16 * i;
            #pragma unroll
            for (int c = 0; c < 8; c++)
                obase[(size_t)r * QDIM + tx + 16 * c] = acc[i][c] * rl[i];
        }
    }
}

// ---------------------------------------------------------------------------
// Launch
// ---------------------------------------------------------------------------
extern "C" void kernel_launch(void* const* d_in, const int* in_sizes, int n_in,
                              void* d_out, int out_size)
{
    const float* x   = (const float*)d_in[0];
    const float* wq  = (const float*)d_in[1];
    const float* bq  = (const float*)d_in[2];
    const float* wkv = (const float*)d_in[3];
    const float* bkv = (const float*)d_in[4];
    const float* wo  = (const float*)d_in[5];
    float* out = (float*)d_out;

    void *pq, *pkv, *patt;
    cudaGetSymbolAddress(&pq,   g_q);
    cudaGetSymbolAddress(&pkv,  g_kv);
    cudaGetSymbolAddress(&patt, g_att);

    // PE table
    pe_init_kernel<<<(T * D + 255) / 256, 256>>>();

    // Q projection (+bias +PE)
    {
        dim3 grid(QDIM / 128, MROWS / 128);
        sgemm_kernel<<<grid, 256>>>(x, wq, bq, (float*)pq, MROWS, QDIM, E, 1);
    }
    // KV projection (+bias +PE on K half)
    {
        dim3 grid(KVDIM / 128, MROWS / 128);
        sgemm_kernel<<<grid, 256>>>(x, wkv, bkv, (float*)pkv, MROWS, KVDIM, E, 2);
    }
    // Flash attention
    {
        size_t smem = sizeof(FlashSmem);
        cudaFuncSetAttribute(flash_kernel, cudaFuncAttributeMaxDynamicSharedMemorySize, (int)smem);
        dim3 grid(T / BR, NH, B);
        flash_kernel<<<grid, 256, smem>>>((const float*)pq, (const float*)pkv, (float*)patt);
    }
    // Output projection
    {
        dim3 grid(E / 128, MROWS / 128);
        sgemm_kernel<<<grid, 256>>>((const float*)patt, wo, nullptr, out, MROWS, E, QDIM, 0);
    }
}

// round 5
// speedup vs baseline: 1.3418x; 1.3418x over previous
#include <cuda_runtime.h>
#include <cuda_bf16.h>
#include <math.h>
#include <stdint.h>

#define B   2
#define T   2048
#define E   2048
#define G   4
#define QPG 4
#define D   128
#define NH  (G*QPG)
#define QDIM (NH*D)     // 2048
#define KVDIM (2*G*D)   // 1024
#define MROWS (B*T)     // 4096

__device__ float g_q  [MROWS * QDIM];
__device__ float g_kv [MROWS * KVDIM];
__device__ float g_att[MROWS * QDIM];
__device__ float g_pe [T * D];

// ---------------- helpers ----------------
__device__ __forceinline__ uint32_t sptr(const void* p) {
    return (uint32_t)__cvta_generic_to_shared(p);
}
__device__ __forceinline__ void ldsm4(uint32_t (&r)[4], uint32_t a) {
    asm volatile("ldmatrix.sync.aligned.m8n8.x4.shared.b16 {%0,%1,%2,%3}, [%4];\n"
                 : "=r"(r[0]), "=r"(r[1]), "=r"(r[2]), "=r"(r[3]) : "r"(a));
}
__device__ __forceinline__ void ldsm4t(uint32_t (&r)[4], uint32_t a) {
    asm volatile("ldmatrix.sync.aligned.m8n8.x4.trans.shared.b16 {%0,%1,%2,%3}, [%4];\n"
                 : "=r"(r[0]), "=r"(r[1]), "=r"(r[2]), "=r"(r[3]) : "r"(a));
}
__device__ __forceinline__ void mma16816(float (&c)[4], const uint32_t (&a)[4], const uint32_t* b) {
    asm volatile(
        "mma.sync.aligned.m16n8k16.row.col.f32.bf16.bf16.f32 "
        "{%0,%1,%2,%3}, {%4,%5,%6,%7}, {%8,%9}, {%0,%1,%2,%3};\n"
        : "+f"(c[0]), "+f"(c[1]), "+f"(c[2]), "+f"(c[3])
        : "r"(a[0]), "r"(a[1]), "r"(a[2]), "r"(a[3]), "r"(b[0]), "r"(b[1]));
}
__device__ __forceinline__ uint32_t pack2(__nv_bfloat16 a, __nv_bfloat16 b) {
    __nv_bfloat162 t; t.x = a; t.y = b;
    return *reinterpret_cast<uint32_t*>(&t);
}
__device__ __forceinline__ void split2(float x0, float x1, uint32_t& h, uint32_t& l) {
    __nv_bfloat16 h0 = __float2bfloat16(x0), h1 = __float2bfloat16(x1);
    __nv_bfloat16 l0 = __float2bfloat16(x0 - __bfloat162float(h0));
    __nv_bfloat16 l1 = __float2bfloat16(x1 - __bfloat162float(h1));
    h = pack2(h0, h1); l = pack2(l0, l1);
}
__device__ __forceinline__ void split4_store(float4 v, __nv_bfloat16* ph, __nv_bfloat16* pl) {
    uint32_t h0, l0, h1, l1;
    split2(v.x, v.y, h0, l0);
    split2(v.z, v.w, h1, l1);
    uint2 hh = make_uint2(h0, h1), ll = make_uint2(l0, l1);
    *reinterpret_cast<uint2*>(ph) = hh;
    *reinterpret_cast<uint2*>(pl) = ll;
}

// ---------------- PE init ----------------
__global__ void pe_init_kernel() {
    int idx = blockIdx.x * blockDim.x + threadIdx.x;
    if (idx >= T * D) return;
    int t = idx / D, d = idx % D;
    float i2  = (float)(d & ~1);
    float inv = expf(-(logf(10000.0f) * i2 / (float)D));
    float ang = (float)t * inv;
    g_pe[idx] = (d & 1) ? cosf(ang) : sinf(ang);
}

// ---------------------------------------------------------------------------
// bf16x3 split tensor-core GEMM: C = A[M,K] @ W[K,N] (+bias)(+PE)
// 128x128x32 block tile, 256 thr (8 warps: 4m x 2n), double-buffered smem.
// mode 0: plain  1: +bias+pe(q)  2: +bias, +pe on k-half (kv)
// ---------------------------------------------------------------------------
#define ASTR 40
#define BSTR 136

struct GemmSmem {
    __nv_bfloat16 As[2][2][128][ASTR];   // [buf][plane hi/lo][m][k]
    __nv_bfloat16 Bs[2][2][32][BSTR];    // [buf][plane][k][n]
};

__global__ __launch_bounds__(256) void gemm_bf16x3_kernel(
    const float* __restrict__ A, const float* __restrict__ W,
    const float* __restrict__ bias, float* __restrict__ C,
    int M, int N, int K, int mode)
{
    extern __shared__ char smraw[];
    GemmSmem* sm = reinterpret_cast<GemmSmem*>(smraw);

    const int tid  = threadIdx.x;
    const int lane = tid & 31;
    const int wid  = tid >> 5;
    const int wm   = wid >> 1;          // 0..3
    const int wn   = wid & 1;           // 0..1
    const int bm = blockIdx.y * 128;
    const int bn = blockIdx.x * 128;

    const int ar = tid >> 1, ac = (tid & 1) * 16;   // A: 128x32
    const int br = tid >> 3, bc = (tid & 7) * 16;   // B: 32x128

    float4 pa[4], pb[4];
    float acc[2][8][4];
    #pragma unroll
    for (int i = 0; i < 2; i++)
        #pragma unroll
        for (int j = 0; j < 8; j++)
            #pragma unroll
            for (int e = 0; e < 4; e++) acc[i][j][e] = 0.f;

    const int NT = K / 32;

    {   // prologue tile 0
        const float* ap = &A[(size_t)(bm + ar) * K + ac];
        const float* bp = &W[(size_t)br * N + bn + bc];
        #pragma unroll
        for (int q = 0; q < 4; q++) {
            float4 va = *reinterpret_cast<const float4*>(ap + q * 4);
            float4 vb = *reinterpret_cast<const float4*>(bp + q * 4);
            split4_store(va, &sm->As[0][0][ar][ac + q * 4], &sm->As[0][1][ar][ac + q * 4]);
            split4_store(vb, &sm->Bs[0][0][br][bc + q * 4], &sm->Bs[0][1][br][bc + q * 4]);
        }
    }
    __syncthreads();

    for (int t = 0; t < NT; t++) {
        const int buf = t & 1;
        if (t + 1 < NT) {
            int k0 = (t + 1) * 32;
            const float* ap = &A[(size_t)(bm + ar) * K + k0 + ac];
            const float* bp = &W[(size_t)(k0 + br) * N + bn + bc];
            #pragma unroll
            for (int q = 0; q < 4; q++) {
                pa[q] = *reinterpret_cast<const float4*>(ap + q * 4);
                pb[q] = *reinterpret_cast<const float4*>(bp + q * 4);
            }
        }

        #pragma unroll
        for (int ks = 0; ks < 2; ks++) {
            uint32_t af[2][2][4];   // [plane][mfrag][reg]
            #pragma unroll
            for (int mf = 0; mf < 2; mf++) {
                ldsm4(af[0][mf], sptr(&sm->As[buf][0][wm * 32 + mf * 16 + (lane & 15)][ks * 16 + (lane >> 4) * 8]));
                ldsm4(af[1][mf], sptr(&sm->As[buf][1][wm * 32 + mf * 16 + (lane & 15)][ks * 16 + (lane >> 4) * 8]));
            }
            #pragma unroll
            for (int np = 0; np < 4; np++) {
                uint32_t bh[4], bl[4];
                ldsm4t(bh, sptr(&sm->Bs[buf][0][ks * 16 + (lane & 15)][wn * 64 + np * 16 + (lane >> 4) * 8]));
                ldsm4t(bl, sptr(&sm->Bs[buf][1][ks * 16 + (lane & 15)][wn * 64 + np * 16 + (lane >> 4) * 8]));
                #pragma unroll
                for (int mf = 0; mf < 2; mf++) {
                    mma16816(acc[mf][2 * np],     af[0][mf], &bh[0]);
                    mma16816(acc[mf][2 * np],     af[1][mf], &bh[0]);
                    mma16816(acc[mf][2 * np],     af[0][mf], &bl[0]);
                    mma16816(acc[mf][2 * np + 1], af[0][mf], &bh[2]);
                    mma16816(acc[mf][2 * np + 1], af[1][mf], &bh[2]);
                    mma16816(acc[mf][2 * np + 1], af[0][mf], &bl[2]);
                }
            }
        }

        if (t + 1 < NT) {
            int nbuf = buf ^ 1;
            #pragma unroll
            for (int q = 0; q < 4; q++) {
                split4_store(pa[q], &sm->As[nbuf][0][ar][ac + q * 4], &sm->As[nbuf][1][ar][ac + q * 4]);
                split4_store(pb[q], &sm->Bs[nbuf][0][br][bc + q * 4], &sm->Bs[nbuf][1][br][bc + q * 4]);
            }
        }
        __syncthreads();
    }

    // epilogue: c0=(r,c) c1=(r,c+1) c2=(r+8,c) c3=(r+8,c+1)
    #pragma unroll
    for (int mf = 0; mf < 2; mf++) {
        #pragma unroll
        for (int nf = 0; nf < 8; nf++) {
            int col = bn + wn * 64 + nf * 8 + (lane & 3) * 2;
            float b0 = 0.f, b1 = 0.f;
            if (mode != 0) { b0 = bias[col]; b1 = bias[col + 1]; }
            #pragma unroll
            for (int half = 0; half < 2; half++) {
                int row = bm + wm * 32 + mf * 16 + (lane >> 2) + half * 8;
                int tt  = row & (T - 1);
                float v0 = acc[mf][nf][half * 2 + 0] + b0;
                float v1 = acc[mf][nf][half * 2 + 1] + b1;
                if (mode == 1) {
                    v0 += g_pe[tt * D + (col & (D - 1))];
                    v1 += g_pe[tt * D + ((col + 1) & (D - 1))];
                } else if (mode == 2) {
                    int dc = col & (2 * D - 1);
                    if (dc < D) {  // k-half; col,col+1 stay in same half (D even offsets)
                        v0 += g_pe[tt * D + dc];
                        v1 += g_pe[tt * D + dc + 1];
                    }
                }
                C[(size_t)row * N + col]     = v0;
                C[(size_t)row * N + col + 1] = v1;
            }
        }
    }
}

// ---------------------------------------------------------------------------
// Flash attention (causal, online softmax) — fp32 SIMT (unchanged this round)
// ---------------------------------------------------------------------------
#define BR 64
#define BC 64
#define KP 132
#define SP 65

struct FlashSmem {
    float Q [BR][KP];
    float Kt[BC][KP];
    float Vt[BC][KP];
    float S [BR][SP];
    float m[BR];
    float l[BR];
    float scale[BR];
};

__global__ __launch_bounds__(256) void flash_kernel(
    const float* __restrict__ Qg, const float* __restrict__ KVg, float* __restrict__ Og)
{
    extern __shared__ float smem_raw[];
    FlashSmem* sm = reinterpret_cast<FlashSmem*>(smem_raw);

    const int tid  = threadIdx.x;
    const int qb   = blockIdx.x * BR;
    const int head = blockIdx.y;
    const int b    = blockIdx.z;
    const int g    = head >> 2;

    const float* qbase  = Qg  + (size_t)b * T * QDIM  + head * D;
    const float* kvbase = KVg + (size_t)b * T * KVDIM + g * (2 * D);
    float*       obase  = Og  + (size_t)b * T * QDIM  + head * D;

    {
        int r0 = tid >> 5;
        int c  = (tid & 31) * 4;
        #pragma unroll
        for (int i = 0; i < 8; i++) {
            int r = r0 + i * 8;
            *reinterpret_cast<float4*>(&sm->Q[r][c]) =
                *reinterpret_cast<const float4*>(&qbase[(size_t)(qb + r) * QDIM + c]);
        }
    }
    if (tid < BR) { sm->m[tid] = -INFINITY; sm->l[tid] = 0.f; }

    const int tx = tid & 15, ty = tid >> 4;

    float acc[4][8];
    #pragma unroll
    for (int i = 0; i < 4; i++)
        #pragma unroll
        for (int c = 0; c < 8; c++) acc[i][c] = 0.f;

    const int ntiles = qb / BC + 1;

    for (int kt = 0; kt < ntiles; kt++) {
        __syncthreads();
        {
            int r0 = tid >> 5;
            int c  = (tid & 31) * 4;
            #pragma unroll
            for (int i = 0; i < 8; i++) {
                int r = r0 + i * 8;
                const float* kvrow = &kvbase[(size_t)(kt * BC + r) * KVDIM];
                *reinterpret_cast<float4*>(&sm->Kt[r][c]) =
                    *reinterpret_cast<const float4*>(&kvrow[c]);
                *reinterpret_cast<float4*>(&sm->Vt[r][c]) =
                    *reinterpret_cast<const float4*>(&kvrow[D + c]);
            }
        }
        __syncthreads();

        {
            float racc[4][4];
            #pragma unroll
            for (int i = 0; i < 4; i++)
                #pragma unroll
                for (int j = 0; j < 4; j++) racc[i][j] = 0.f;

            #pragma unroll 4
            for (int k4 = 0; k4 < D; k4 += 4) {
                float4 qa[4], kb[4];
                #pragma unroll
                for (int i = 0; i < 4; i++)
                    qa[i] = *reinterpret_cast<const float4*>(&sm->Q[ty + 16 * i][k4]);
                #pragma unroll
                for (int j = 0; j < 4; j++)
                    kb[j] = *reinterpret_cast<const float4*>(&sm->Kt[tx + 16 * j][k4]);
                #pragma unroll
                for (int i = 0; i < 4; i++)
                    #pragma unroll
                    for (int j = 0; j < 4; j++) {
                        racc[i][j] = fmaf(qa[i].x, kb[j].x, racc[i][j]);
                        racc[i][j] = fmaf(qa[i].y, kb[j].y, racc[i][j]);
                        racc[i][j] = fmaf(qa[i].z, kb[j].z, racc[i][j]);
                        racc[i][j] = fmaf(qa[i].w, kb[j].w, racc[i][j]);
                    }
            }
            const float sc = 0.08838834764831845f;
            #pragma unroll
            for (int i = 0; i < 4; i++)
                #pragma unroll
                for (int j = 0; j < 4; j++)
                    sm->S[ty + 16 * i][tx + 16 * j] = racc[i][j] * sc;
        }
        __syncthreads();

        {
            int r     = tid >> 2;
            int part  = tid & 3;
            int row_g = qb + r;
            float vals[16];
            float mx = -INFINITY;
            #pragma unroll
            for (int c = 0; c < 16; c++) {
                int cc = part * 16 + c;
                float s = sm->S[r][cc];
                s = ((kt * BC + cc) <= row_g) ? s : -INFINITY;
                vals[c] = s;
                mx = fmaxf(mx, s);
            }
            mx = fmaxf(mx, __shfl_xor_sync(0xFFFFFFFF, mx, 1));
            mx = fmaxf(mx, __shfl_xor_sync(0xFFFFFFFF, mx, 2));
            float m_old = sm->m[r];
            float m_new = fmaxf(m_old, mx);
            float sum = 0.f;
            #pragma unroll
            for (int c = 0; c < 16; c++) {
                float p = __expf(vals[c] - m_new);
                sm->S[r][part * 16 + c] = p;
                sum += p;
            }
            sum += __shfl_xor_sync(0xFFFFFFFF, sum, 1);
            sum += __shfl_xor_sync(0xFFFFFFFF, sum, 2);
            if (part == 0) {
                float scl = __expf(m_old - m_new);
                sm->scale[r] = scl;
                sm->l[r] = sm->l[r] * scl + sum;
                sm->m[r] = m_new;
            }
        }
        __syncthreads();

        {
            float rs[4];
            #pragma unroll
            for (int i = 0; i < 4; i++) rs[i] = sm->scale[ty + 16 * i];
            #pragma unroll
            for (int i = 0; i < 4; i++)
                #pragma unroll
                for (int c = 0; c < 8; c++) acc[i][c] *= rs[i];

            #pragma unroll 2
            for (int j = 0; j < BC; j++) {
                float p[4];
                #pragma unroll
                for (int i = 0; i < 4; i++) p[i] = sm->S[ty + 16 * i][j];
                float vv[8];
                #pragma unroll
                for (int c = 0; c < 8; c++) vv[c] = sm->Vt[j][tx + 16 * c];
                #pragma unroll
                for (int i = 0; i < 4; i++)
                    #pragma unroll
                    for (int c = 0; c < 8; c++)
                        acc[i][c] = fmaf(p[i], vv[c], acc[i][c]);
            }
        }
    }
    __syncthreads();

    {
        float rl[4];
        #pragma unroll
        for (int i = 0; i < 4; i++) rl[i] = 1.f / sm->l[ty + 16 * i];
        #pragma unroll
        for (int i = 0; i < 4; i++) {
            int r = qb + ty + 16 * i;
            #pragma unroll
            for (int c = 0; c < 8; c++)
                obase[(size_t)r * QDIM + tx + 16 * c] = acc[i][c] * rl[i];
        }
    }
}

// ---------------------------------------------------------------------------
// Launch
// ---------------------------------------------------------------------------
extern "C" void kernel_launch(void* const* d_in, const int* in_sizes, int n_in,
                              void* d_out, int out_size)
{
    const float* x   = (const float*)d_in[0];
    const float* wq  = (const float*)d_in[1];
    const float* bq  = (const float*)d_in[2];
    const float* wkv = (const float*)d_in[3];
    const float* bkv = (const float*)d_in[4];
    const float* wo  = (const float*)d_in[5];
    float* out = (float*)d_out;

    void *pq, *pkv, *patt;
    cudaGetSymbolAddress(&pq,   g_q);
    cudaGetSymbolAddress(&pkv,  g_kv);
    cudaGetSymbolAddress(&patt, g_att);

    pe_init_kernel<<<(T * D + 255) / 256, 256>>>();

    size_t gsmem = sizeof(GemmSmem);
    static int gset = 0;
    if (!gset) {
        cudaFuncSetAttribute(gemm_bf16x3_kernel, cudaFuncAttributeMaxDynamicSharedMemorySize, (int)gsmem);
        cudaFuncSetAttribute(flash_kernel, cudaFuncAttributeMaxDynamicSharedMemorySize, (int)sizeof(FlashSmem));
        gset = 1;
    }

    {   // Q projection (+bias +PE)
        dim3 grid(QDIM / 128, MROWS / 128);
        gemm_bf16x3_kernel<<<grid, 256, gsmem>>>(x, wq, bq, (float*)pq, MROWS, QDIM, E, 1);
    }
    {   // KV projection (+bias, +PE on K half)
        dim3 grid(KVDIM / 128, MROWS / 128);
        gemm_bf16x3_kernel<<<grid, 256, gsmem>>>(x, wkv, bkv, (float*)pkv, MROWS, KVDIM, E, 2);
    }
    {   // Flash attention
        dim3 grid(T / BR, NH, B);
        flash_kernel<<<grid, 256, sizeof(FlashSmem)>>>((const float*)pq, (const float*)pkv, (float*)patt);
    }
    {   // Output projection
        dim3 grid(E / 128, MROWS / 128);
        gemm_bf16x3_kernel<<<grid, 256, gsmem>>>((const float*)patt, wo, nullptr, out, MROWS, E, QDIM, 0);
    }
}

// round 7
// speedup vs baseline: 2.2561x; 1.6813x over previous
#include <cuda_runtime.h>
#include <cuda_bf16.h>
#include <math.h>
#include <stdint.h>

#define B   2
#define T   2048
#define E   2048
#define G   4
#define QPG 4
#define D   128
#define NH  (G*QPG)
#define QDIM (NH*D)     // 2048
#define KVDIM (2*G*D)   // 1024
#define MROWS (B*T)     // 4096

__device__ float g_q  [MROWS * QDIM];
__device__ float g_kv [MROWS * KVDIM];
__device__ float g_att[MROWS * QDIM];
__device__ float g_pe [T * D];

// ---------------- helpers ----------------
__device__ __forceinline__ uint32_t sptr(const void* p) {
    return (uint32_t)__cvta_generic_to_shared(p);
}
__device__ __forceinline__ void ldsm4(uint32_t (&r)[4], uint32_t a) {
    asm volatile("ldmatrix.sync.aligned.m8n8.x4.shared.b16 {%0,%1,%2,%3}, [%4];\n"
                 : "=r"(r[0]), "=r"(r[1]), "=r"(r[2]), "=r"(r[3]) : "r"(a));
}
__device__ __forceinline__ void ldsm4t(uint32_t (&r)[4], uint32_t a) {
    asm volatile("ldmatrix.sync.aligned.m8n8.x4.trans.shared.b16 {%0,%1,%2,%3}, [%4];\n"
                 : "=r"(r[0]), "=r"(r[1]), "=r"(r[2]), "=r"(r[3]) : "r"(a));
}
__device__ __forceinline__ void mma16816(float (&c)[4], const uint32_t (&a)[4], const uint32_t* b) {
    asm volatile(
        "mma.sync.aligned.m16n8k16.row.col.f32.bf16.bf16.f32 "
        "{%0,%1,%2,%3}, {%4,%5,%6,%7}, {%8,%9}, {%0,%1,%2,%3};\n"
        : "+f"(c[0]), "+f"(c[1]), "+f"(c[2]), "+f"(c[3])
        : "r"(a[0]), "r"(a[1]), "r"(a[2]), "r"(a[3]), "r"(b[0]), "r"(b[1]));
}
__device__ __forceinline__ uint32_t pack2(__nv_bfloat16 a, __nv_bfloat16 b) {
    __nv_bfloat162 t; t.x = a; t.y = b;
    return *reinterpret_cast<uint32_t*>(&t);
}
__device__ __forceinline__ void split2(float x0, float x1, uint32_t& h, uint32_t& l) {
    __nv_bfloat16 h0 = __float2bfloat16(x0), h1 = __float2bfloat16(x1);
    __nv_bfloat16 l0 = __float2bfloat16(x0 - __bfloat162float(h0));
    __nv_bfloat16 l1 = __float2bfloat16(x1 - __bfloat162float(h1));
    h = pack2(h0, h1); l = pack2(l0, l1);
}
__device__ __forceinline__ void split4_store(float4 v, __nv_bfloat16* ph, __nv_bfloat16* pl) {
    uint32_t h0, l0, h1, l1;
    split2(v.x, v.y, h0, l0);
    split2(v.z, v.w, h1, l1);
    uint2 hh = make_uint2(h0, h1), ll = make_uint2(l0, l1);
    *reinterpret_cast<uint2*>(ph) = hh;
    *reinterpret_cast<uint2*>(pl) = ll;
}

// ---------------- PE init ----------------
__global__ void pe_init_kernel() {
    int idx = blockIdx.x * blockDim.x + threadIdx.x;
    if (idx >= T * D) return;
    int t = idx / D, d = idx % D;
    float i2  = (float)(d & ~1);
    float inv = expf(-(logf(10000.0f) * i2 / (float)D));
    float ang = (float)t * inv;
    g_pe[idx] = (d & 1) ? cosf(ang) : sinf(ang);
}

// ---------------------------------------------------------------------------
// bf16x3 split tensor-core GEMM: C = A[M,K] @ W[K,N] (+bias)(+PE)  (unchanged)
// ---------------------------------------------------------------------------
#define ASTR 40
#define BSTR 136

struct GemmSmem {
    __nv_bfloat16 As[2][2][128][ASTR];
    __nv_bfloat16 Bs[2][2][32][BSTR];
};

__global__ __launch_bounds__(256) void gemm_bf16x3_kernel(
    const float* __restrict__ A, const float* __restrict__ W,
    const float* __restrict__ bias, float* __restrict__ C,
    int M, int N, int K, int mode)
{
    extern __shared__ char smraw[];
    GemmSmem* sm = reinterpret_cast<GemmSmem*>(smraw);

    const int tid  = threadIdx.x;
    const int lane = tid & 31;
    const int wid  = tid >> 5;
    const int wm   = wid >> 1;
    const int wn   = wid & 1;
    const int bm = blockIdx.y * 128;
    const int bn = blockIdx.x * 128;

    const int ar = tid >> 1, ac = (tid & 1) * 16;
    const int br = tid >> 3, bc = (tid & 7) * 16;

    float4 pa[4], pb[4];
    float acc[2][8][4];
    #pragma unroll
    for (int i = 0; i < 2; i++)
        #pragma unroll
        for (int j = 0; j < 8; j++)
            #pragma unroll
            for (int e = 0; e < 4; e++) acc[i][j][e] = 0.f;

    const int NT = K / 32;

    {
        const float* ap = &A[(size_t)(bm + ar) * K + ac];
        const float* bp = &W[(size_t)br * N + bn + bc];
        #pragma unroll
        for (int q = 0; q < 4; q++) {
            float4 va = *reinterpret_cast<const float4*>(ap + q * 4);
            float4 vb = *reinterpret_cast<const float4*>(bp + q * 4);
            split4_store(va, &sm->As[0][0][ar][ac + q * 4], &sm->As[0][1][ar][ac + q * 4]);
            split4_store(vb, &sm->Bs[0][0][br][bc + q * 4], &sm->Bs[0][1][br][bc + q * 4]);
        }
    }
    __syncthreads();

    for (int t = 0; t < NT; t++) {
        const int buf = t & 1;
        if (t + 1 < NT) {
            int k0 = (t + 1) * 32;
            const float* ap = &A[(size_t)(bm + ar) * K + k0 + ac];
            const float* bp = &W[(size_t)(k0 + br) * N + bn + bc];
            #pragma unroll
            for (int q = 0; q < 4; q++) {
                pa[q] = *reinterpret_cast<const float4*>(ap + q * 4);
                pb[q] = *reinterpret_cast<const float4*>(bp + q * 4);
            }
        }

        #pragma unroll
        for (int ks = 0; ks < 2; ks++) {
            uint32_t af[2][2][4];
            #pragma unroll
            for (int mf = 0; mf < 2; mf++) {
                ldsm4(af[0][mf], sptr(&sm->As[buf][0][wm * 32 + mf * 16 + (lane & 15)][ks * 16 + (lane >> 4) * 8]));
                ldsm4(af[1][mf], sptr(&sm->As[buf][1][wm * 32 + mf * 16 + (lane & 15)][ks * 16 + (lane >> 4) * 8]));
            }
            #pragma unroll
            for (int np = 0; np < 4; np++) {
                uint32_t bh[4], bl[4];
                ldsm4t(bh, sptr(&sm->Bs[buf][0][ks * 16 + (lane & 15)][wn * 64 + np * 16 + (lane >> 4) * 8]));
                ldsm4t(bl, sptr(&sm->Bs[buf][1][ks * 16 + (lane & 15)][wn * 64 + np * 16 + (lane >> 4) * 8]));
                #pragma unroll
                for (int mf = 0; mf < 2; mf++) {
                    mma16816(acc[mf][2 * np],     af[0][mf], &bh[0]);
                    mma16816(acc[mf][2 * np],     af[1][mf], &bh[0]);
                    mma16816(acc[mf][2 * np],     af[0][mf], &bl[0]);
                    mma16816(acc[mf][2 * np + 1], af[0][mf], &bh[2]);
                    mma16816(acc[mf][2 * np + 1], af[1][mf], &bh[2]);
                    mma16816(acc[mf][2 * np + 1], af[0][mf], &bl[2]);
                }
            }
        }

        if (t + 1 < NT) {
            int nbuf = buf ^ 1;
            #pragma unroll
            for (int q = 0; q < 4; q++) {
                split4_store(pa[q], &sm->As[nbuf][0][ar][ac + q * 4], &sm->As[nbuf][1][ar][ac + q * 4]);
                split4_store(pb[q], &sm->Bs[nbuf][0][br][bc + q * 4], &sm->Bs[nbuf][1][br][bc + q * 4]);
            }
        }
        __syncthreads();
    }

    #pragma unroll
    for (int mf = 0; mf < 2; mf++) {
        #pragma unroll
        for (int nf = 0; nf < 8; nf++) {
            int col = bn + wn * 64 + nf * 8 + (lane & 3) * 2;
            float b0 = 0.f, b1 = 0.f;
            if (mode != 0) { b0 = bias[col]; b1 = bias[col + 1]; }
            #pragma unroll
            for (int half = 0; half < 2; half++) {
                int row = bm + wm * 32 + mf * 16 + (lane >> 2) + half * 8;
                int tt  = row & (T - 1);
                float v0 = acc[mf][nf][half * 2 + 0] + b0;
                float v1 = acc[mf][nf][half * 2 + 1] + b1;
                if (mode == 1) {
                    v0 += g_pe[tt * D + (col & (D - 1))];
                    v1 += g_pe[tt * D + ((col + 1) & (D - 1))];
                } else if (mode == 2) {
                    int dc = col & (2 * D - 1);
                    if (dc < D) {
                        v0 += g_pe[tt * D + dc];
                        v1 += g_pe[tt * D + dc + 1];
                    }
                }
                C[(size_t)row * N + col]     = v0;
                C[(size_t)row * N + col + 1] = v1;
            }
        }
    }
}

// ---------------------------------------------------------------------------
// Flash attention — bf16x3 tensor-core version.
// 128 threads / 4 warps, BR=BC=64, D=128. Warp w owns query rows w*16..w*16+15.
// QK^T: Q A-frags (ldsm4), K row-major consumed as B-frags via {r0,r2}/{r1,r3}.
// Softmax + P hi/lo split entirely in register fragments (FA2 layout identity).
// PV: V row-major [key][d] via ldsm4t (proven GEMM Bs pattern).
// ---------------------------------------------------------------------------
#define FSTR 136

struct FlashSmem {
    __nv_bfloat16 Q[2][64][FSTR];   // [plane hi/lo][row][d]
    __nv_bfloat16 K[2][64][FSTR];   // [plane][key][d]
    __nv_bfloat16 V[2][64][FSTR];   // [plane][key][d]
};

__global__ __launch_bounds__(128) void flash_mma_kernel(
    const float* __restrict__ Qg, const float* __restrict__ KVg, float* __restrict__ Og)
{
    extern __shared__ char smraw[];
    FlashSmem* sm = reinterpret_cast<FlashSmem*>(smraw);

    const int tid  = threadIdx.x;
    const int lane = tid & 31;
    const int w    = tid >> 5;
    const int qb   = blockIdx.x * 64;
    const int head = blockIdx.y;
    const int b    = blockIdx.z;
    const int g    = head >> 2;

    const float* qbase  = Qg  + (size_t)b * T * QDIM  + head * D;
    const float* kvbase = KVg + (size_t)b * T * KVDIM + g * (2 * D);
    float*       obase  = Og  + (size_t)b * T * QDIM  + head * D;

    // Load Q tile (64 x 128 fp32 -> hi/lo bf16)
    #pragma unroll
    for (int i = 0; i < 16; i++) {
        int pos = i * 128 + tid;
        int r = pos >> 5, c = (pos & 31) * 4;
        float4 v = *reinterpret_cast<const float4*>(&qbase[(size_t)(qb + r) * QDIM + c]);
        split4_store(v, &sm->Q[0][r][c], &sm->Q[1][r][c]);
    }

    float o[16][4];
    #pragma unroll
    for (int nf = 0; nf < 16; nf++)
        #pragma unroll
        for (int e = 0; e < 4; e++) o[nf][e] = 0.f;

    float m0 = -INFINITY, m1 = -INFINITY, l0 = 0.f, l1 = 0.f;

    const int ntiles = qb / 64 + 1;
    const int cc   = (lane & 3) * 2;
    const int row0 = qb + w * 16 + (lane >> 2);
    const int row1 = row0 + 8;

    for (int kt = 0; kt < ntiles; kt++) {
        __syncthreads();
        // Load K,V tile (64 x 128 each)
        #pragma unroll
        for (int i = 0; i < 16; i++) {
            int pos = i * 128 + tid;
            int r = pos >> 5, c = (pos & 31) * 4;
            const float* kvrow = &kvbase[(size_t)(kt * 64 + r) * KVDIM];
            float4 kv4 = *reinterpret_cast<const float4*>(&kvrow[c]);
            float4 vv4 = *reinterpret_cast<const float4*>(&kvrow[D + c]);
            split4_store(kv4, &sm->K[0][r][c], &sm->K[1][r][c]);
            split4_store(vv4, &sm->V[0][r][c], &sm->V[1][r][c]);
        }
        __syncthreads();

        // ---- QK^T ----
        float s[8][4];
        #pragma unroll
        for (int j = 0; j < 8; j++)
            #pragma unroll
            for (int e = 0; e < 4; e++) s[j][e] = 0.f;

        #pragma unroll
        for (int ks = 0; ks < 8; ks++) {
            uint32_t qh[4], ql[4];
            ldsm4(qh, sptr(&sm->Q[0][w * 16 + (lane & 15)][ks * 16 + (lane >> 4) * 8]));
            ldsm4(ql, sptr(&sm->Q[1][w * 16 + (lane & 15)][ks * 16 + (lane >> 4) * 8]));
            #pragma unroll
            for (int j = 0; j < 4; j++) {
                uint32_t kh[4], kl[4];
                ldsm4(kh, sptr(&sm->K[0][j * 16 + (lane & 15)][ks * 16 + (lane >> 4) * 8]));
                ldsm4(kl, sptr(&sm->K[1][j * 16 + (lane & 15)][ks * 16 + (lane >> 4) * 8]));
                uint32_t b0h[2] = {kh[0], kh[2]}, b1h[2] = {kh[1], kh[3]};
                uint32_t b0l[2] = {kl[0], kl[2]}, b1l[2] = {kl[1], kl[3]};
                mma16816(s[2 * j],     qh, b0h);
                mma16816(s[2 * j],     ql, b0h);
                mma16816(s[2 * j],     qh, b0l);
                mma16816(s[2 * j + 1], qh, b1h);
                mma16816(s[2 * j + 1], ql, b1h);
                mma16816(s[2 * j + 1], qh, b1l);
            }
        }

        // ---- scale + causal mask + online softmax (registers) ----
        const float scale = 0.08838834764831845f;  // 1/sqrt(128)
        const bool maskt = (kt == ntiles - 1);
        float mx0 = -INFINITY, mx1 = -INFINITY;
        #pragma unroll
        for (int j = 0; j < 8; j++) {
            int colb = kt * 64 + j * 8 + cc;
            #pragma unroll
            for (int e = 0; e < 4; e++) {
                float v = s[j][e] * scale;
                if (maskt) {
                    int col = colb + (e & 1);
                    int rw  = (e < 2) ? row0 : row1;
                    if (col > rw) v = -INFINITY;
                }
                s[j][e] = v;
            }
            mx0 = fmaxf(mx0, fmaxf(s[j][0], s[j][1]));
            mx1 = fmaxf(mx1, fmaxf(s[j][2], s[j][3]));
        }
        mx0 = fmaxf(mx0, __shfl_xor_sync(0xFFFFFFFF, mx0, 1));
        mx0 = fmaxf(mx0, __shfl_xor_sync(0xFFFFFFFF, mx0, 2));
        mx1 = fmaxf(mx1, __shfl_xor_sync(0xFFFFFFFF, mx1, 1));
        mx1 = fmaxf(mx1, __shfl_xor_sync(0xFFFFFFFF, mx1, 2));

        float mn0 = fmaxf(m0, mx0), mn1 = fmaxf(m1, mx1);
        float f0 = __expf(m0 - mn0), f1 = __expf(m1 - mn1);
        float sum0 = 0.f, sum1 = 0.f;
        #pragma unroll
        for (int j = 0; j < 8; j++) {
            s[j][0] = __expf(s[j][0] - mn0);
            s[j][1] = __expf(s[j][1] - mn0);
            s[j][2] = __expf(s[j][2] - mn1);
            s[j][3] = __expf(s[j][3] - mn1);
            sum0 += s[j][0] + s[j][1];
            sum1 += s[j][2] + s[j][3];
        }
        sum0 += __shfl_xor_sync(0xFFFFFFFF, sum0, 1);
        sum0 += __shfl_xor_sync(0xFFFFFFFF, sum0, 2);
        sum1 += __shfl_xor_sync(0xFFFFFFFF, sum1, 1);
        sum1 += __shfl_xor_sync(0xFFFFFFFF, sum1, 2);
        l0 = l0 * f0 + sum0; m0 = mn0;
        l1 = l1 * f1 + sum1; m1 = mn1;

        #pragma unroll
        for (int nf = 0; nf < 16; nf++) {
            o[nf][0] *= f0; o[nf][1] *= f0;
            o[nf][2] *= f1; o[nf][3] *= f1;
        }

        // ---- P @ V ----
        #pragma unroll
        for (int kk = 0; kk < 4; kk++) {
            uint32_t ph[4], pl[4];
            split2(s[2 * kk][0],     s[2 * kk][1],     ph[0], pl[0]);
            split2(s[2 * kk][2],     s[2 * kk][3],     ph[1], pl[1]);
            split2(s[2 * kk + 1][0], s[2 * kk + 1][1], ph[2], pl[2]);
            split2(s[2 * kk + 1][2], s[2 * kk + 1][3], ph[3], pl[3]);
            #pragma unroll
            for (int j = 0; j < 8; j++) {
                uint32_t vh[4], vl[4];
                ldsm4t(vh, sptr(&sm->V[0][kk * 16 + (lane & 15)][j * 16 + (lane >> 4) * 8]));
                ldsm4t(vl, sptr(&sm->V[1][kk * 16 + (lane & 15)][j * 16 + (lane >> 4) * 8]));
                mma16816(o[2 * j],     ph, &vh[0]);
                mma16816(o[2 * j],     pl, &vh[0]);
                mma16816(o[2 * j],     ph, &vl[0]);
                mma16816(o[2 * j + 1], ph, &vh[2]);
                mma16816(o[2 * j + 1], pl, &vh[2]);
                mma16816(o[2 * j + 1], ph, &vl[2]);
            }
        }
    }

    // ---- epilogue ----
    float il0 = 1.f / l0, il1 = 1.f / l1;
    #pragma unroll
    for (int nf = 0; nf < 16; nf++) {
        int col = nf * 8 + cc;
        *reinterpret_cast<float2*>(&obase[(size_t)row0 * QDIM + col]) =
            make_float2(o[nf][0] * il0, o[nf][1] * il0);
        *reinterpret_cast<float2*>(&obase[(size_t)row1 * QDIM + col]) =
            make_float2(o[nf][2] * il1, o[nf][3] * il1);
    }
}

// ---------------------------------------------------------------------------
// Launch
// ---------------------------------------------------------------------------
extern "C" void kernel_launch(void* const* d_in, const int* in_sizes, int n_in,
                              void* d_out, int out_size)
{
    const float* x   = (const float*)d_in[0];
    const float* wq  = (const float*)d_in[1];
    const float* bq  = (const float*)d_in[2];
    const float* wkv = (const float*)d_in[3];
    const float* bkv = (const float*)d_in[4];
    const float* wo  = (const float*)d_in[5];
    float* out = (float*)d_out;

    void *pq, *pkv, *patt;
    cudaGetSymbolAddress(&pq,   g_q);
    cudaGetSymbolAddress(&pkv,  g_kv);
    cudaGetSymbolAddress(&patt, g_att);

    pe_init_kernel<<<(T * D + 255) / 256, 256>>>();

    const size_t gsmem = sizeof(GemmSmem);
    const size_t fsmem = sizeof(FlashSmem);
    cudaFuncSetAttribute(gemm_bf16x3_kernel, cudaFuncAttributeMaxDynamicSharedMemorySize, (int)gsmem);
    cudaFuncSetAttribute(flash_mma_kernel,   cudaFuncAttributeMaxDynamicSharedMemorySize, (int)fsmem);

    {   // Q projection (+bias +PE)
        dim3 grid(QDIM / 128, MROWS / 128);
        gemm_bf16x3_kernel<<<grid, 256, gsmem>>>(x, wq, bq, (float*)pq, MROWS, QDIM, E, 1);
    }
    {   // KV projection (+bias, +PE on K half)
        dim3 grid(KVDIM / 128, MROWS / 128);
        gemm_bf16x3_kernel<<<grid, 256, gsmem>>>(x, wkv, bkv, (float*)pkv, MROWS, KVDIM, E, 2);
    }
    {   // Flash attention (tensor core)
        dim3 grid(T / 64, NH, B);
        flash_mma_kernel<<<grid, 128, fsmem>>>((const float*)pq, (const float*)pkv, (float*)patt);
    }
    {   // Output projection
        dim3 grid(E / 128, MROWS / 128);
        gemm_bf16x3_kernel<<<grid, 256, gsmem>>>((const float*)patt, wo, nullptr, out, MROWS, E, QDIM, 0);
    }
}

// round 8
// speedup vs baseline: 2.5106x; 1.1128x over previous
#include <cuda_runtime.h>
#include <cuda_bf16.h>
#include <math.h>
#include <stdint.h>

#define B   2
#define T   2048
#define E   2048
#define G   4
#define QPG 4
#define D   128
#define NH  (G*QPG)
#define QDIM (NH*D)     // 2048
#define KVDIM (2*G*D)   // 1024
#define MROWS (B*T)     // 4096

// bf16 hi/lo plane scratch (device globals; no allocations allowed)
__device__ __nv_bfloat16 g_xh [MROWS * E];
__device__ __nv_bfloat16 g_xl [MROWS * E];
__device__ __nv_bfloat16 g_wqh[E * QDIM];
__device__ __nv_bfloat16 g_wql[E * QDIM];
__device__ __nv_bfloat16 g_wkvh[E * KVDIM];
__device__ __nv_bfloat16 g_wkvl[E * KVDIM];
__device__ __nv_bfloat16 g_woh[QDIM * E];
__device__ __nv_bfloat16 g_wol[QDIM * E];
__device__ __nv_bfloat16 g_qh [MROWS * QDIM];
__device__ __nv_bfloat16 g_ql [MROWS * QDIM];
__device__ __nv_bfloat16 g_kvh[MROWS * KVDIM];
__device__ __nv_bfloat16 g_kvl[MROWS * KVDIM];
__device__ __nv_bfloat16 g_ah [MROWS * QDIM];
__device__ __nv_bfloat16 g_al [MROWS * QDIM];
__device__ float g_pe[T * D];

// ---------------- helpers ----------------
__device__ __forceinline__ uint32_t sptr(const void* p) {
    return (uint32_t)__cvta_generic_to_shared(p);
}
__device__ __forceinline__ void ldsm4(uint32_t (&r)[4], uint32_t a) {
    asm volatile("ldmatrix.sync.aligned.m8n8.x4.shared.b16 {%0,%1,%2,%3}, [%4];\n"
                 : "=r"(r[0]), "=r"(r[1]), "=r"(r[2]), "=r"(r[3]) : "r"(a));
}
__device__ __forceinline__ void ldsm4t(uint32_t (&r)[4], uint32_t a) {
    asm volatile("ldmatrix.sync.aligned.m8n8.x4.trans.shared.b16 {%0,%1,%2,%3}, [%4];\n"
                 : "=r"(r[0]), "=r"(r[1]), "=r"(r[2]), "=r"(r[3]) : "r"(a));
}
__device__ __forceinline__ void mma16816(float (&c)[4], const uint32_t (&a)[4], const uint32_t* b) {
    asm volatile(
        "mma.sync.aligned.m16n8k16.row.col.f32.bf16.bf16.f32 "
        "{%0,%1,%2,%3}, {%4,%5,%6,%7}, {%8,%9}, {%0,%1,%2,%3};\n"
        : "+f"(c[0]), "+f"(c[1]), "+f"(c[2]), "+f"(c[3])
        : "r"(a[0]), "r"(a[1]), "r"(a[2]), "r"(a[3]), "r"(b[0]), "r"(b[1]));
}
__device__ __forceinline__ uint32_t pack2(__nv_bfloat16 a, __nv_bfloat16 b) {
    __nv_bfloat162 t; t.x = a; t.y = b;
    return *reinterpret_cast<uint32_t*>(&t);
}
__device__ __forceinline__ void split2(float x0, float x1, uint32_t& h, uint32_t& l) {
    __nv_bfloat16 h0 = __float2bfloat16(x0), h1 = __float2bfloat16(x1);
    __nv_bfloat16 l0 = __float2bfloat16(x0 - __bfloat162float(h0));
    __nv_bfloat16 l1 = __float2bfloat16(x1 - __bfloat162float(h1));
    h = pack2(h0, h1); l = pack2(l0, l1);
}

// ---------------- pre-pass: fp32 -> hi/lo bf16 planes ----------------
__global__ void split_kernel(const float* __restrict__ src,
                             __nv_bfloat16* __restrict__ h,
                             __nv_bfloat16* __restrict__ l, int n4)
{
    int i = blockIdx.x * blockDim.x + threadIdx.x;
    if (i >= n4) return;
    float4 v = reinterpret_cast<const float4*>(src)[i];
    uint32_t h0, l0, h1, l1;
    split2(v.x, v.y, h0, l0);
    split2(v.z, v.w, h1, l1);
    reinterpret_cast<uint2*>(h)[i] = make_uint2(h0, h1);
    reinterpret_cast<uint2*>(l)[i] = make_uint2(l0, l1);
}

// ---------------- PE init ----------------
__global__ void pe_init_kernel() {
    int idx = blockIdx.x * blockDim.x + threadIdx.x;
    if (idx >= T * D) return;
    int t = idx / D, d = idx % D;
    float i2  = (float)(d & ~1);
    float inv = expf(-(logf(10000.0f) * i2 / (float)D));
    float ang = (float)t * inv;
    g_pe[idx] = (d & 1) ? cosf(ang) : sinf(ang);
}

// ---------------------------------------------------------------------------
// bf16x3 split tensor-core GEMM on pre-split planes.
// C = (Ah+Al)[M,K] @ (Wh+Wl)[K,N] (+bias)(+PE)
// mode 0: fp32 out   mode 1: +bias+pe -> bf16 planes (q)
// mode 2: +bias, +pe on k-half -> bf16 planes (kv)
// ---------------------------------------------------------------------------
#define ASTR 40
#define BSTR 136

struct GemmSmem {
    __nv_bfloat16 As[2][2][128][ASTR];   // [buf][plane][m][k]
    __nv_bfloat16 Bs[2][2][32][BSTR];    // [buf][plane][k][n]
};

__global__ __launch_bounds__(256) void gemm_bf16x3_kernel(
    const __nv_bfloat16* __restrict__ Ah, const __nv_bfloat16* __restrict__ Al,
    const __nv_bfloat16* __restrict__ Wh, const __nv_bfloat16* __restrict__ Wl,
    const float* __restrict__ bias,
    __nv_bfloat16* __restrict__ Ch, __nv_bfloat16* __restrict__ Cl,
    float* __restrict__ Cf,
    int M, int N, int K, int mode)
{
    extern __shared__ char smraw[];
    GemmSmem* sm = reinterpret_cast<GemmSmem*>(smraw);

    const int tid  = threadIdx.x;
    const int lane = tid & 31;
    const int wid  = tid >> 5;
    const int wm   = wid >> 1;
    const int wn   = wid & 1;
    const int bm = blockIdx.y * 128;
    const int bn = blockIdx.x * 128;

    const int ar = tid >> 1, ac = (tid & 1) * 16;   // A tile 128x32, 16 bf16/thread/plane
    const int br = tid >> 3, bc = (tid & 7) * 16;   // B tile 32x128

    float acc[2][8][4];
    #pragma unroll
    for (int i = 0; i < 2; i++)
        #pragma unroll
        for (int j = 0; j < 8; j++)
            #pragma unroll
            for (int e = 0; e < 4; e++) acc[i][j][e] = 0.f;

    const int NT = K / 32;

    {   // prologue tile 0
        const uint4* ah = reinterpret_cast<const uint4*>(&Ah[(size_t)(bm + ar) * K + ac]);
        const uint4* al = reinterpret_cast<const uint4*>(&Al[(size_t)(bm + ar) * K + ac]);
        const uint4* wh = reinterpret_cast<const uint4*>(&Wh[(size_t)br * N + bn + bc]);
        const uint4* wl = reinterpret_cast<const uint4*>(&Wl[(size_t)br * N + bn + bc]);
        *reinterpret_cast<uint4*>(&sm->As[0][0][ar][ac])     = ah[0];
        *reinterpret_cast<uint4*>(&sm->As[0][0][ar][ac + 8]) = ah[1];
        *reinterpret_cast<uint4*>(&sm->As[0][1][ar][ac])     = al[0];
        *reinterpret_cast<uint4*>(&sm->As[0][1][ar][ac + 8]) = al[1];
        *reinterpret_cast<uint4*>(&sm->Bs[0][0][br][bc])     = wh[0];
        *reinterpret_cast<uint4*>(&sm->Bs[0][0][br][bc + 8]) = wh[1];
        *reinterpret_cast<uint4*>(&sm->Bs[0][1][br][bc])     = wl[0];
        *reinterpret_cast<uint4*>(&sm->Bs[0][1][br][bc + 8]) = wl[1];
    }
    __syncthreads();

    uint4 pah0, pah1, pal0, pal1, pbh0, pbh1, pbl0, pbl1;

    for (int t = 0; t < NT; t++) {
        const int buf = t & 1;
        if (t + 1 < NT) {
            int k0 = (t + 1) * 32;
            const uint4* ah = reinterpret_cast<const uint4*>(&Ah[(size_t)(bm + ar) * K + k0 + ac]);
            const uint4* al = reinterpret_cast<const uint4*>(&Al[(size_t)(bm + ar) * K + k0 + ac]);
            const uint4* wh = reinterpret_cast<const uint4*>(&Wh[(size_t)(k0 + br) * N + bn + bc]);
            const uint4* wl = reinterpret_cast<const uint4*>(&Wl[(size_t)(k0 + br) * N + bn + bc]);
            pah0 = ah[0]; pah1 = ah[1];
            pal0 = al[0]; pal1 = al[1];
            pbh0 = wh[0]; pbh1 = wh[1];
            pbl0 = wl[0]; pbl1 = wl[1];
        }

        #pragma unroll
        for (int ks = 0; ks < 2; ks++) {
            uint32_t af[2][2][4];
            #pragma unroll
            for (int mf = 0; mf < 2; mf++) {
                ldsm4(af[0][mf], sptr(&sm->As[buf][0][wm * 32 + mf * 16 + (lane & 15)][ks * 16 + (lane >> 4) * 8]));
                ldsm4(af[1][mf], sptr(&sm->As[buf][1][wm * 32 + mf * 16 + (lane & 15)][ks * 16 + (lane >> 4) * 8]));
            }
            #pragma unroll
            for (int np = 0; np < 4; np++) {
                uint32_t bh[4], bl[4];
                ldsm4t(bh, sptr(&sm->Bs[buf][0][ks * 16 + (lane & 15)][wn * 64 + np * 16 + (lane >> 4) * 8]));
                ldsm4t(bl, sptr(&sm->Bs[buf][1][ks * 16 + (lane & 15)][wn * 64 + np * 16 + (lane >> 4) * 8]));
                #pragma unroll
                for (int mf = 0; mf < 2; mf++) {
                    mma16816(acc[mf][2 * np],     af[0][mf], &bh[0]);
                    mma16816(acc[mf][2 * np],     af[1][mf], &bh[0]);
                    mma16816(acc[mf][2 * np],     af[0][mf], &bl[0]);
                    mma16816(acc[mf][2 * np + 1], af[0][mf], &bh[2]);
                    mma16816(acc[mf][2 * np + 1], af[1][mf], &bh[2]);
                    mma16816(acc[mf][2 * np + 1], af[0][mf], &bl[2]);
                }
            }
        }

        if (t + 1 < NT) {
            int nbuf = buf ^ 1;
            *reinterpret_cast<uint4*>(&sm->As[nbuf][0][ar][ac])     = pah0;
            *reinterpret_cast<uint4*>(&sm->As[nbuf][0][ar][ac + 8]) = pah1;
            *reinterpret_cast<uint4*>(&sm->As[nbuf][1][ar][ac])     = pal0;
            *reinterpret_cast<uint4*>(&sm->As[nbuf][1][ar][ac + 8]) = pal1;
            *reinterpret_cast<uint4*>(&sm->Bs[nbuf][0][br][bc])     = pbh0;
            *reinterpret_cast<uint4*>(&sm->Bs[nbuf][0][br][bc + 8]) = pbh1;
            *reinterpret_cast<uint4*>(&sm->Bs[nbuf][1][br][bc])     = pbl0;
            *reinterpret_cast<uint4*>(&sm->Bs[nbuf][1][br][bc + 8]) = pbl1;
        }
        __syncthreads();
    }

    // epilogue: acc fragment c0=(r,c) c1=(r,c+1) c2=(r+8,c) c3=(r+8,c+1)
    #pragma unroll
    for (int mf = 0; mf < 2; mf++) {
        #pragma unroll
        for (int nf = 0; nf < 8; nf++) {
            int col = bn + wn * 64 + nf * 8 + (lane & 3) * 2;
            float b0 = 0.f, b1 = 0.f;
            if (mode != 0) { b0 = bias[col]; b1 = bias[col + 1]; }
            #pragma unroll
            for (int half = 0; half < 2; half++) {
                int row = bm + wm * 32 + mf * 16 + (lane >> 2) + half * 8;
                int tt  = row & (T - 1);
                float v0 = acc[mf][nf][half * 2 + 0] + b0;
                float v1 = acc[mf][nf][half * 2 + 1] + b1;
                if (mode == 0) {
                    Cf[(size_t)row * N + col]     = v0;
                    Cf[(size_t)row * N + col + 1] = v1;
                } else {
                    if (mode == 1) {
                        v0 += g_pe[tt * D + (col & (D - 1))];
                        v1 += g_pe[tt * D + ((col + 1) & (D - 1))];
                    } else {
                        int dc = col & (2 * D - 1);
                        if (dc < D) {
                            v0 += g_pe[tt * D + dc];
                            v1 += g_pe[tt * D + dc + 1];
                        }
                    }
                    uint32_t h, l;
                    split2(v0, v1, h, l);
                    *reinterpret_cast<uint32_t*>(&Ch[(size_t)row * N + col]) = h;
                    *reinterpret_cast<uint32_t*>(&Cl[(size_t)row * N + col]) = l;
                }
            }
        }
    }
}

// ---------------------------------------------------------------------------
// Flash attention — bf16x3 tensor-core, pre-split plane I/O.
// 128 threads / 4 warps, BR=BC=64, D=128. Warp w owns query rows w*16..w*16+15.
// ---------------------------------------------------------------------------
#define FSTR 136

struct FlashSmem {
    __nv_bfloat16 Q[2][64][FSTR];   // [plane][row][d]
    __nv_bfloat16 K[2][64][FSTR];
    __nv_bfloat16 V[2][64][FSTR];
};

__global__ __launch_bounds__(128) void flash_mma_kernel(
    const __nv_bfloat16* __restrict__ Qh, const __nv_bfloat16* __restrict__ Ql,
    const __nv_bfloat16* __restrict__ KVh, const __nv_bfloat16* __restrict__ KVl,
    __nv_bfloat16* __restrict__ Ah, __nv_bfloat16* __restrict__ Al)
{
    extern __shared__ char smraw[];
    FlashSmem* sm = reinterpret_cast<FlashSmem*>(smraw);

    const int tid  = threadIdx.x;
    const int lane = tid & 31;
    const int w    = tid >> 5;
    const int qb   = blockIdx.x * 64;
    const int head = blockIdx.y;
    const int b    = blockIdx.z;
    const int g    = head >> 2;

    const size_t qoff  = (size_t)b * T * QDIM  + head * D;
    const size_t kvoff = (size_t)b * T * KVDIM + g * (2 * D);

    // Load Q tile planes (64 x 128 bf16 each): 8 uint4 per thread per plane
    #pragma unroll
    for (int i = 0; i < 8; i++) {
        int pos = i * 128 + tid;
        int r = pos >> 4, c = (pos & 15) * 8;
        size_t go = qoff + (size_t)(qb + r) * QDIM + c;
        *reinterpret_cast<uint4*>(&sm->Q[0][r][c]) = *reinterpret_cast<const uint4*>(&Qh[go]);
        *reinterpret_cast<uint4*>(&sm->Q[1][r][c]) = *reinterpret_cast<const uint4*>(&Ql[go]);
    }

    float o[16][4];
    #pragma unroll
    for (int nf = 0; nf < 16; nf++)
        #pragma unroll
        for (int e = 0; e < 4; e++) o[nf][e] = 0.f;

    float m0 = -INFINITY, m1 = -INFINITY, l0 = 0.f, l1 = 0.f;

    const int ntiles = qb / 64 + 1;
    const int cc   = (lane & 3) * 2;
    const int row0 = qb + w * 16 + (lane >> 2);
    const int row1 = row0 + 8;

    for (int kt = 0; kt < ntiles; kt++) {
        __syncthreads();
        // Load K,V tile planes
        #pragma unroll
        for (int i = 0; i < 8; i++) {
            int pos = i * 128 + tid;
            int r = pos >> 4, c = (pos & 15) * 8;
            size_t go = kvoff + (size_t)(kt * 64 + r) * KVDIM + c;
            *reinterpret_cast<uint4*>(&sm->K[0][r][c]) = *reinterpret_cast<const uint4*>(&KVh[go]);
            *reinterpret_cast<uint4*>(&sm->K[1][r][c]) = *reinterpret_cast<const uint4*>(&KVl[go]);
            *reinterpret_cast<uint4*>(&sm->V[0][r][c]) = *reinterpret_cast<const uint4*>(&KVh[go + D]);
            *reinterpret_cast<uint4*>(&sm->V[1][r][c]) = *reinterpret_cast<const uint4*>(&KVl[go + D]);
        }
        __syncthreads();

        // ---- QK^T ----
        float s[8][4];
        #pragma unroll
        for (int j = 0; j < 8; j++)
            #pragma unroll
            for (int e = 0; e < 4; e++) s[j][e] = 0.f;

        #pragma unroll
        for (int ks = 0; ks < 8; ks++) {
            uint32_t qh[4], ql[4];
            ldsm4(qh, sptr(&sm->Q[0][w * 16 + (lane & 15)][ks * 16 + (lane >> 4) * 8]));
            ldsm4(ql, sptr(&sm->Q[1][w * 16 + (lane & 15)][ks * 16 + (lane >> 4) * 8]));
            #pragma unroll
            for (int j = 0; j < 4; j++) {
                uint32_t kh[4], kl[4];
                ldsm4(kh, sptr(&sm->K[0][j * 16 + (lane & 15)][ks * 16 + (lane >> 4) * 8]));
                ldsm4(kl, sptr(&sm->K[1][j * 16 + (lane & 15)][ks * 16 + (lane >> 4) * 8]));
                uint32_t b0h[2] = {kh[0], kh[2]}, b1h[2] = {kh[1], kh[3]};
                uint32_t b0l[2] = {kl[0], kl[2]}, b1l[2] = {kl[1], kl[3]};
                mma16816(s[2 * j],     qh, b0h);
                mma16816(s[2 * j],     ql, b0h);
                mma16816(s[2 * j],     qh, b0l);
                mma16816(s[2 * j + 1], qh, b1h);
                mma16816(s[2 * j + 1], ql, b1h);
                mma16816(s[2 * j + 1], qh, b1l);
            }
        }

        // ---- scale + causal mask + online softmax ----
        const float scale = 0.08838834764831845f;
        const bool maskt = (kt == ntiles - 1);
        float mx0 = -INFINITY, mx1 = -INFINITY;
        #pragma unroll
        for (int j = 0; j < 8; j++) {
            int colb = kt * 64 + j * 8 + cc;
            #pragma unroll
            for (int e = 0; e < 4; e++) {
                float v = s[j][e] * scale;
                if (maskt) {
                    int col = colb + (e & 1);
                    int rw  = (e < 2) ? row0 : row1;
                    if (col > rw) v = -INFINITY;
                }
                s[j][e] = v;
            }
            mx0 = fmaxf(mx0, fmaxf(s[j][0], s[j][1]));
            mx1 = fmaxf(mx1, fmaxf(s[j][2], s[j][3]));
        }
        mx0 = fmaxf(mx0, __shfl_xor_sync(0xFFFFFFFF, mx0, 1));
        mx0 = fmaxf(mx0, __shfl_xor_sync(0xFFFFFFFF, mx0, 2));
        mx1 = fmaxf(mx1, __shfl_xor_sync(0xFFFFFFFF, mx1, 1));
        mx1 = fmaxf(mx1, __shfl_xor_sync(0xFFFFFFFF, mx1, 2));

        float mn0 = fmaxf(m0, mx0), mn1 = fmaxf(m1, mx1);
        float f0 = __expf(m0 - mn0), f1 = __expf(m1 - mn1);
        float sum0 = 0.f, sum1 = 0.f;
        #pragma unroll
        for (int j = 0; j < 8; j++) {
            s[j][0] = __expf(s[j][0] - mn0);
            s[j][1] = __expf(s[j][1] - mn0);
            s[j][2] = __expf(s[j][2] - mn1);
            s[j][3] = __expf(s[j][3] - mn1);
            sum0 += s[j][0] + s[j][1];
            sum1 += s[j][2] + s[j][3];
        }
        sum0 += __shfl_xor_sync(0xFFFFFFFF, sum0, 1);
        sum0 += __shfl_xor_sync(0xFFFFFFFF, sum0, 2);
        sum1 += __shfl_xor_sync(0xFFFFFFFF, sum1, 1);
        sum1 += __shfl_xor_sync(0xFFFFFFFF, sum1, 2);
        l0 = l0 * f0 + sum0; m0 = mn0;
        l1 = l1 * f1 + sum1; m1 = mn1;

        #pragma unroll
        for (int nf = 0; nf < 16; nf++) {
            o[nf][0] *= f0; o[nf][1] *= f0;
            o[nf][2] *= f1; o[nf][3] *= f1;
        }

        // ---- P @ V ----
        #pragma unroll
        for (int kk = 0; kk < 4; kk++) {
            uint32_t ph[4], pl[4];
            split2(s[2 * kk][0],     s[2 * kk][1],     ph[0], pl[0]);
            split2(s[2 * kk][2],     s[2 * kk][3],     ph[1], pl[1]);
            split2(s[2 * kk + 1][0], s[2 * kk + 1][1], ph[2], pl[2]);
            split2(s[2 * kk + 1][2], s[2 * kk + 1][3], ph[3], pl[3]);
            #pragma unroll
            for (int j = 0; j < 8; j++) {
                uint32_t vh[4], vl[4];
                ldsm4t(vh, sptr(&sm->V[0][kk * 16 + (lane & 15)][j * 16 + (lane >> 4) * 8]));
                ldsm4t(vl, sptr(&sm->V[1][kk * 16 + (lane & 15)][j * 16 + (lane >> 4) * 8]));
                mma16816(o[2 * j],     ph, &vh[0]);
                mma16816(o[2 * j],     pl, &vh[0]);
                mma16816(o[2 * j],     ph, &vl[0]);
                mma16816(o[2 * j + 1], ph, &vh[2]);
                mma16816(o[2 * j + 1], pl, &vh[2]);
                mma16816(o[2 * j + 1], ph, &vl[2]);
            }
        }
    }

    // ---- epilogue: write hi/lo planes ----
    float il0 = 1.f / l0, il1 = 1.f / l1;
    #pragma unroll
    for (int nf = 0; nf < 16; nf++) {
        int col = nf * 8 + cc;
        uint32_t h, l;
        split2(o[nf][0] * il0, o[nf][1] * il0, h, l);
        *reinterpret_cast<uint32_t*>(&Ah[qoff + (size_t)row0 * QDIM + col]) = h;
        *reinterpret_cast<uint32_t*>(&Al[qoff + (size_t)row0 * QDIM + col]) = l;
        split2(o[nf][2] * il1, o[nf][3] * il1, h, l);
        *reinterpret_cast<uint32_t*>(&Ah[qoff + (size_t)row1 * QDIM + col]) = h;
        *reinterpret_cast<uint32_t*>(&Al[qoff + (size_t)row1 * QDIM + col]) = l;
    }
}

// ---------------------------------------------------------------------------
// Launch
// ---------------------------------------------------------------------------
extern "C" void kernel_launch(void* const* d_in, const int* in_sizes, int n_in,
                              void* d_out, int out_size)
{
    const float* x   = (const float*)d_in[0];
    const float* wq  = (const float*)d_in[1];
    const float* bq  = (const float*)d_in[2];
    const float* wkv = (const float*)d_in[3];
    const float* bkv = (const float*)d_in[4];
    const float* wo  = (const float*)d_in[5];
    float* out = (float*)d_out;

    void *pxh, *pxl, *pwqh, *pwql, *pwkvh, *pwkvl, *pwoh, *pwol;
    void *pqh, *pql, *pkvh, *pkvl, *pah, *pal;
    cudaGetSymbolAddress(&pxh,  g_xh);   cudaGetSymbolAddress(&pxl,  g_xl);
    cudaGetSymbolAddress(&pwqh, g_wqh);  cudaGetSymbolAddress(&pwql, g_wql);
    cudaGetSymbolAddress(&pwkvh,g_wkvh); cudaGetSymbolAddress(&pwkvl,g_wkvl);
    cudaGetSymbolAddress(&pwoh, g_woh);  cudaGetSymbolAddress(&pwol, g_wol);
    cudaGetSymbolAddress(&pqh,  g_qh);   cudaGetSymbolAddress(&pql,  g_ql);
    cudaGetSymbolAddress(&pkvh, g_kvh);  cudaGetSymbolAddress(&pkvl, g_kvl);
    cudaGetSymbolAddress(&pah,  g_ah);   cudaGetSymbolAddress(&pal,  g_al);

    pe_init_kernel<<<(T * D + 255) / 256, 256>>>();

    // pre-split inputs & weights into bf16 hi/lo planes
    {
        int n4;
        n4 = MROWS * E / 4;
        split_kernel<<<(n4 + 255) / 256, 256>>>(x, (__nv_bfloat16*)pxh, (__nv_bfloat16*)pxl, n4);
        n4 = E * QDIM / 4;
        split_kernel<<<(n4 + 255) / 256, 256>>>(wq, (__nv_bfloat16*)pwqh, (__nv_bfloat16*)pwql, n4);
        n4 = E * KVDIM / 4;
        split_kernel<<<(n4 + 255) / 256, 256>>>(wkv, (__nv_bfloat16*)pwkvh, (__nv_bfloat16*)pwkvl, n4);
        n4 = QDIM * E / 4;
        split_kernel<<<(n4 + 255) / 256, 256>>>(wo, (__nv_bfloat16*)pwoh, (__nv_bfloat16*)pwol, n4);
    }

    const size_t gsmem = sizeof(GemmSmem);
    const size_t fsmem = sizeof(FlashSmem);
    cudaFuncSetAttribute(gemm_bf16x3_kernel, cudaFuncAttributeMaxDynamicSharedMemorySize, (int)gsmem);
    cudaFuncSetAttribute(flash_mma_kernel,   cudaFuncAttributeMaxDynamicSharedMemorySize, (int)fsmem);

    {   // Q projection (+bias +PE) -> q planes
        dim3 grid(QDIM / 128, MROWS / 128);
        gemm_bf16x3_kernel<<<grid, 256, gsmem>>>(
            (const __nv_bfloat16*)pxh, (const __nv_bfloat16*)pxl,
            (const __nv_bfloat16*)pwqh, (const __nv_bfloat16*)pwql,
            bq, (__nv_bfloat16*)pqh, (__nv_bfloat16*)pql, nullptr,
            MROWS, QDIM, E, 1);
    }
    {   // KV projection (+bias, +PE on K half) -> kv planes
        dim3 grid(KVDIM / 128, MROWS / 128);
        gemm_bf16x3_kernel<<<grid, 256, gsmem>>>(
            (const __nv_bfloat16*)pxh, (const __nv_bfloat16*)pxl,
            (const __nv_bfloat16*)pwkvh, (const __nv_bfloat16*)pwkvl,
            bkv, (__nv_bfloat16*)pkvh, (__nv_bfloat16*)pkvl, nullptr,
            MROWS, KVDIM, E, 2);
    }
    {   // Flash attention -> att planes
        dim3 grid(T / 64, NH, B);
        flash_mma_kernel<<<grid, 128, fsmem>>>(
            (const __nv_bfloat16*)pqh, (const __nv_bfloat16*)pql,
            (const __nv_bfloat16*)pkvh, (const __nv_bfloat16*)pkvl,
            (__nv_bfloat16*)pah, (__nv_bfloat16*)pal);
    }
    {   // Output projection -> fp32 out
        dim3 grid(E / 128, MROWS / 128);
        gemm_bf16x3_kernel<<<grid, 256, gsmem>>>(
            (const __nv_bfloat16*)pah, (const __nv_bfloat16*)pal,
            (const __nv_bfloat16*)pwoh, (const __nv_bfloat16*)pwol,
            nullptr, nullptr, nullptr, out,
            MROWS, E, QDIM, 0);
    }
}

// round 13
// speedup vs baseline: 2.5646x; 1.0215x over previous
#include <cuda_runtime.h>
#include <cuda_bf16.h>
#include <math.h>
#include <stdint.h>

#define B   2
#define T   2048
#define E   2048
#define G   4
#define QPG 4
#define D   128
#define NH  (G*QPG)
#define QDIM (NH*D)     // 2048
#define KVDIM (2*G*D)   // 1024
#define MROWS (B*T)     // 4096

// bf16 hi/lo plane scratch (device globals; no allocations allowed)
__device__ __nv_bfloat16 g_xh [MROWS * E];
__device__ __nv_bfloat16 g_xl [MROWS * E];
__device__ __nv_bfloat16 g_wqh[E * QDIM];
__device__ __nv_bfloat16 g_wql[E * QDIM];
__device__ __nv_bfloat16 g_wkvh[E * KVDIM];
__device__ __nv_bfloat16 g_wkvl[E * KVDIM];
__device__ __nv_bfloat16 g_woh[QDIM * E];
__device__ __nv_bfloat16 g_wol[QDIM * E];
__device__ __nv_bfloat16 g_qh [MROWS * QDIM];
__device__ __nv_bfloat16 g_ql [MROWS * QDIM];
__device__ __nv_bfloat16 g_kvh[MROWS * KVDIM];
__device__ __nv_bfloat16 g_kvl[MROWS * KVDIM];
__device__ __nv_bfloat16 g_ah [MROWS * QDIM];
__device__ __nv_bfloat16 g_al [MROWS * QDIM];
__device__ float g_pe[T * D];

// ---------------- helpers ----------------
__device__ __forceinline__ uint32_t sptr(const void* p) {
    return (uint32_t)__cvta_generic_to_shared(p);
}
__device__ __forceinline__ void ldsm4(uint32_t (&r)[4], uint32_t a) {
    asm volatile("ldmatrix.sync.aligned.m8n8.x4.shared.b16 {%0,%1,%2,%3}, [%4];\n"
                 : "=r"(r[0]), "=r"(r[1]), "=r"(r[2]), "=r"(r[3]) : "r"(a));
}
__device__ __forceinline__ void ldsm4t(uint32_t (&r)[4], uint32_t a) {
    asm volatile("ldmatrix.sync.aligned.m8n8.x4.trans.shared.b16 {%0,%1,%2,%3}, [%4];\n"
                 : "=r"(r[0]), "=r"(r[1]), "=r"(r[2]), "=r"(r[3]) : "r"(a));
}
__device__ __forceinline__ void mma16816(float (&c)[4], const uint32_t (&a)[4], const uint32_t* b) {
    asm volatile(
        "mma.sync.aligned.m16n8k16.row.col.f32.bf16.bf16.f32 "
        "{%0,%1,%2,%3}, {%4,%5,%6,%7}, {%8,%9}, {%0,%1,%2,%3};\n"
        : "+f"(c[0]), "+f"(c[1]), "+f"(c[2]), "+f"(c[3])
        : "r"(a[0]), "r"(a[1]), "r"(a[2]), "r"(a[3]), "r"(b[0]), "r"(b[1]));
}
__device__ __forceinline__ uint32_t pack2(__nv_bfloat16 a, __nv_bfloat16 b) {
    __nv_bfloat162 t; t.x = a; t.y = b;
    return *reinterpret_cast<uint32_t*>(&t);
}
__device__ __forceinline__ void split2(float x0, float x1, uint32_t& h, uint32_t& l) {
    __nv_bfloat16 h0 = __float2bfloat16(x0), h1 = __float2bfloat16(x1);
    __nv_bfloat16 l0 = __float2bfloat16(x0 - __bfloat162float(h0));
    __nv_bfloat16 l1 = __float2bfloat16(x1 - __bfloat162float(h1));
    h = pack2(h0, h1); l = pack2(l0, l1);
}
__device__ __forceinline__ void cp16(uint32_t dst, const void* src) {
    asm volatile("cp.async.cg.shared.global [%0], [%1], 16;\n" :: "r"(dst), "l"(src));
}
__device__ __forceinline__ void cp_commit() {
    asm volatile("cp.async.commit_group;\n" ::: "memory");
}
template <int N>
__device__ __forceinline__ void cp_wait() {
    asm volatile("cp.async.wait_group %0;\n" :: "n"(N) : "memory");
}

// ---------------- pre-pass: fp32 -> hi/lo bf16 planes ----------------
__global__ void split_kernel(const float* __restrict__ src,
                             __nv_bfloat16* __restrict__ h,
                             __nv_bfloat16* __restrict__ l, int n4)
{
    int i = blockIdx.x * blockDim.x + threadIdx.x;
    if (i >= n4) return;
    float4 v = reinterpret_cast<const float4*>(src)[i];
    uint32_t h0, l0, h1, l1;
    split2(v.x, v.y, h0, l0);
    split2(v.z, v.w, h1, l1);
    reinterpret_cast<uint2*>(h)[i] = make_uint2(h0, h1);
    reinterpret_cast<uint2*>(l)[i] = make_uint2(l0, l1);
}

// ---------------- PE init ----------------
__global__ void pe_init_kernel() {
    int idx = blockIdx.x * blockDim.x + threadIdx.x;
    if (idx >= T * D) return;
    int t = idx / D, d = idx % D;
    float i2  = (float)(d & ~1);
    float inv = expf(-(logf(10000.0f) * i2 / (float)D));
    float ang = (float)t * inv;
    g_pe[idx] = (d & 1) ? cosf(ang) : sinf(ang);
}

// ---------------------------------------------------------------------------
// bf16x3 split tensor-core GEMM on pre-split planes.
// 128x128x32 tile, 128 threads / 4 warps (2m x 2n), 64x64 warp tile.
// cp.async double-buffered smem. mode 0: fp32 out  1: q planes  2: kv planes
// ---------------------------------------------------------------------------
#define ASTR 40
#define BSTR 136

struct GemmSmem {
    __nv_bfloat16 As[2][2][128][ASTR];   // [buf][plane][m][k]
    __nv_bfloat16 Bs[2][2][32][BSTR];    // [buf][plane][k][n]
};

__global__ __launch_bounds__(128) void gemm_bf16x3_kernel(
    const __nv_bfloat16* __restrict__ Ah, const __nv_bfloat16* __restrict__ Al,
    const __nv_bfloat16* __restrict__ Wh, const __nv_bfloat16* __restrict__ Wl,
    const float* __restrict__ bias,
    __nv_bfloat16* __restrict__ Ch, __nv_bfloat16* __restrict__ Cl,
    float* __restrict__ Cf,
    int M, int N, int K, int mode)
{
    extern __shared__ char smraw[];
    GemmSmem* sm = reinterpret_cast<GemmSmem*>(smraw);

    const int tid  = threadIdx.x;
    const int lane = tid & 31;
    const int wid  = tid >> 5;
    const int wm   = wid >> 1;          // 0..1 (64-row block)
    const int wn   = wid & 1;           // 0..1 (64-col block)
    const int bm = blockIdx.y * 128;
    const int bn = blockIdx.x * 128;

    // loaders (128 threads):
    // A: 128 rows x 32 cols/plane; thread covers rows (tid>>1)+{0,64}, cols (tid&1)*16 .. +16
    const int ar = tid >> 1, ac = (tid & 1) * 16;
    // B: 32 rows x 128 cols/plane; thread covers rows (tid>>3)+{0,16}, cols (tid&7)*16 .. +16
    const int br = tid >> 3, bc = (tid & 7) * 16;

    float acc[4][8][4];
    #pragma unroll
    for (int i = 0; i < 4; i++)
        #pragma unroll
        for (int j = 0; j < 8; j++)
            #pragma unroll
            for (int e = 0; e < 4; e++) acc[i][j][e] = 0.f;

    const int NT = K / 32;

    // async-load one K-chunk into buffer `bf`
    auto load_chunk = [&](int t, int bf) {
        const int k0 = t * 32;
        #pragma unroll
        for (int h = 0; h < 2; h++) {
            int r = ar + h * 64;
            const __nv_bfloat16* gah = &Ah[(size_t)(bm + r) * K + k0 + ac];
            const __nv_bfloat16* gal = &Al[(size_t)(bm + r) * K + k0 + ac];
            cp16(sptr(&sm->As[bf][0][r][ac]),     gah);
            cp16(sptr(&sm->As[bf][0][r][ac + 8]), gah + 8);
            cp16(sptr(&sm->As[bf][1][r][ac]),     gal);
            cp16(sptr(&sm->As[bf][1][r][ac + 8]), gal + 8);
        }
        #pragma unroll
        for (int h = 0; h < 2; h++) {
            int r = br + h * 16;
            const __nv_bfloat16* gwh = &Wh[(size_t)(k0 + r) * N + bn + bc];
            const __nv_bfloat16* gwl = &Wl[(size_t)(k0 + r) * N + bn + bc];
            cp16(sptr(&sm->Bs[bf][0][r][bc]),     gwh);
            cp16(sptr(&sm->Bs[bf][0][r][bc + 8]), gwh + 8);
            cp16(sptr(&sm->Bs[bf][1][r][bc]),     gwl);
            cp16(sptr(&sm->Bs[bf][1][r][bc + 8]), gwl + 8);
        }
        cp_commit();
    };

    load_chunk(0, 0);

    for (int t = 0; t < NT; t++) {
        const int buf = t & 1;
        if (t + 1 < NT) {
            load_chunk(t + 1, buf ^ 1);
            cp_wait<1>();
        } else {
            cp_wait<0>();
        }
        __syncthreads();

        #pragma unroll
        for (int ks = 0; ks < 2; ks++) {
            uint32_t af[2][4][4];   // [plane][mfrag]
            #pragma unroll
            for (int mf = 0; mf < 4; mf++) {
                ldsm4(af[0][mf], sptr(&sm->As[buf][0][wm * 64 + mf * 16 + (lane & 15)][ks * 16 + (lane >> 4) * 8]));
                ldsm4(af[1][mf], sptr(&sm->As[buf][1][wm * 64 + mf * 16 + (lane & 15)][ks * 16 + (lane >> 4) * 8]));
            }
            #pragma unroll
            for (int np = 0; np < 4; np++) {
                uint32_t bh[4], bl[4];
                ldsm4t(bh, sptr(&sm->Bs[buf][0][ks * 16 + (lane & 15)][wn * 64 + np * 16 + (lane >> 4) * 8]));
                ldsm4t(bl, sptr(&sm->Bs[buf][1][ks * 16 + (lane & 15)][wn * 64 + np * 16 + (lane >> 4) * 8]));
                #pragma unroll
                for (int mf = 0; mf < 4; mf++) {
                    mma16816(acc[mf][2 * np],     af[0][mf], &bh[0]);
                    mma16816(acc[mf][2 * np],     af[1][mf], &bh[0]);
                    mma16816(acc[mf][2 * np],     af[0][mf], &bl[0]);
                    mma16816(acc[mf][2 * np + 1], af[0][mf], &bh[2]);
                    mma16816(acc[mf][2 * np + 1], af[1][mf], &bh[2]);
                    mma16816(acc[mf][2 * np + 1], af[0][mf], &bl[2]);
                }
            }
        }
        __syncthreads();
    }

    // epilogue: fragment c0=(r,c) c1=(r,c+1) c2=(r+8,c) c3=(r+8,c+1)
    #pragma unroll
    for (int mf = 0; mf < 4; mf++) {
        #pragma unroll
        for (int nf = 0; nf < 8; nf++) {
            int col = bn + wn * 64 + nf * 8 + (lane & 3) * 2;
            float b0 = 0.f, b1 = 0.f;
            if (mode != 0) { b0 = bias[col]; b1 = bias[col + 1]; }
            #pragma unroll
            for (int half = 0; half < 2; half++) {
                int row = bm + wm * 64 + mf * 16 + (lane >> 2) + half * 8;
                int tt  = row & (T - 1);
                float v0 = acc[mf][nf][half * 2 + 0] + b0;
                float v1 = acc[mf][nf][half * 2 + 1] + b1;
                if (mode == 0) {
                    Cf[(size_t)row * N + col]     = v0;
                    Cf[(size_t)row * N + col + 1] = v1;
                } else {
                    if (mode == 1) {
                        v0 += g_pe[tt * D + (col & (D - 1))];
                        v1 += g_pe[tt * D + ((col + 1) & (D - 1))];
                    } else {
                        int dc = col & (2 * D - 1);
                        if (dc < D) {
                            v0 += g_pe[tt * D + dc];
                            v1 += g_pe[tt * D + dc + 1];
                        }
                    }
                    uint32_t h, l;
                    split2(v0, v1, h, l);
                    *reinterpret_cast<uint32_t*>(&Ch[(size_t)row * N + col]) = h;
                    *reinterpret_cast<uint32_t*>(&Cl[(size_t)row * N + col]) = l;
                }
            }
        }
    }
}

// ---------------------------------------------------------------------------
// Flash attention — bf16x3 mma.sync, plane I/O (unchanged from R8 passing)
// ---------------------------------------------------------------------------
#define FSTR 136

struct FlashSmem {
    __nv_bfloat16 Q[2][64][FSTR];
    __nv_bfloat16 K[2][64][FSTR];
    __nv_bfloat16 V[2][64][FSTR];
};

__global__ __launch_bounds__(128) void flash_mma_kernel(
    const __nv_bfloat16* __restrict__ Qh, const __nv_bfloat16* __restrict__ Ql,
    const __nv_bfloat16* __restrict__ KVh, const __nv_bfloat16* __restrict__ KVl,
    __nv_bfloat16* __restrict__ Ah, __nv_bfloat16* __restrict__ Al)
{
    extern __shared__ char smraw[];
    FlashSmem* sm = reinterpret_cast<FlashSmem*>(smraw);

    const int tid  = threadIdx.x;
    const int lane = tid & 31;
    const int w    = tid >> 5;
    const int qb   = blockIdx.x * 64;
    const int head = blockIdx.y;
    const int b    = blockIdx.z;
    const int g    = head >> 2;

    const size_t qoff  = (size_t)b * T * QDIM  + head * D;
    const size_t kvoff = (size_t)b * T * KVDIM + g * (2 * D);

    #pragma unroll
    for (int i = 0; i < 8; i++) {
        int pos = i * 128 + tid;
        int r = pos >> 4, c = (pos & 15) * 8;
        size_t go = qoff + (size_t)(qb + r) * QDIM + c;
        *reinterpret_cast<uint4*>(&sm->Q[0][r][c]) = *reinterpret_cast<const uint4*>(&Qh[go]);
        *reinterpret_cast<uint4*>(&sm->Q[1][r][c]) = *reinterpret_cast<const uint4*>(&Ql[go]);
    }

    float o[16][4];
    #pragma unroll
    for (int nf = 0; nf < 16; nf++)
        #pragma unroll
        for (int e = 0; e < 4; e++) o[nf][e] = 0.f;

    float m0 = -INFINITY, m1 = -INFINITY, l0 = 0.f, l1 = 0.f;

    const int ntiles = qb / 64 + 1;
    const int cc   = (lane & 3) * 2;
    const int row0 = qb + w * 16 + (lane >> 2);
    const int row1 = row0 + 8;

    for (int kt = 0; kt < ntiles; kt++) {
        __syncthreads();
        #pragma unroll
        for (int i = 0; i < 8; i++) {
            int pos = i * 128 + tid;
            int r = pos >> 4, c = (pos & 15) * 8;
            size_t go = kvoff + (size_t)(kt * 64 + r) * KVDIM + c;
            *reinterpret_cast<uint4*>(&sm->K[0][r][c]) = *reinterpret_cast<const uint4*>(&KVh[go]);
            *reinterpret_cast<uint4*>(&sm->K[1][r][c]) = *reinterpret_cast<const uint4*>(&KVl[go]);
            *reinterpret_cast<uint4*>(&sm->V[0][r][c]) = *reinterpret_cast<const uint4*>(&KVh[go + D]);
            *reinterpret_cast<uint4*>(&sm->V[1][r][c]) = *reinterpret_cast<const uint4*>(&KVl[go + D]);
        }
        __syncthreads();

        float s[8][4];
        #pragma unroll
        for (int j = 0; j < 8; j++)
            #pragma unroll
            for (int e = 0; e < 4; e++) s[j][e] = 0.f;

        #pragma unroll
        for (int ks = 0; ks < 8; ks++) {
            uint32_t qh[4], ql[4];
            ldsm4(qh, sptr(&sm->Q[0][w * 16 + (lane & 15)][ks * 16 + (lane >> 4) * 8]));
            ldsm4(ql, sptr(&sm->Q[1][w * 16 + (lane & 15)][ks * 16 + (lane >> 4) * 8]));
            #pragma unroll
            for (int j = 0; j < 4; j++) {
                uint32_t kh[4], kl[4];
                ldsm4(kh, sptr(&sm->K[0][j * 16 + (lane & 15)][ks * 16 + (lane >> 4) * 8]));
                ldsm4(kl, sptr(&sm->K[1][j * 16 + (lane & 15)][ks * 16 + (lane >> 4) * 8]));
                uint32_t b0h[2] = {kh[0], kh[2]}, b1h[2] = {kh[1], kh[3]};
                uint32_t b0l[2] = {kl[0], kl[2]}, b1l[2] = {kl[1], kl[3]};
                mma16816(s[2 * j],     qh, b0h);
                mma16816(s[2 * j],     ql, b0h);
                mma16816(s[2 * j],     qh, b0l);
                mma16816(s[2 * j + 1], qh, b1h);
                mma16816(s[2 * j + 1], ql, b1h);
                mma16816(s[2 * j + 1], qh, b1l);
            }
        }

        const float scale = 0.08838834764831845f;
        const bool maskt = (kt == ntiles - 1);
        float mx0 = -INFINITY, mx1 = -INFINITY;
        #pragma unroll
        for (int j = 0; j < 8; j++) {
            int colb = kt * 64 + j * 8 + cc;
            #pragma unroll
            for (int e = 0; e < 4; e++) {
                float v = s[j][e] * scale;
                if (maskt) {
                    int col = colb + (e & 1);
                    int rw  = (e < 2) ? row0 : row1;
                    if (col > rw) v = -INFINITY;
                }
                s[j][e] = v;
            }
            mx0 = fmaxf(mx0, fmaxf(s[j][0], s[j][1]));
            mx1 = fmaxf(mx1, fmaxf(s[j][2], s[j][3]));
        }
        mx0 = fmaxf(mx0, __shfl_xor_sync(0xFFFFFFFF, mx0, 1));
        mx0 = fmaxf(mx0, __shfl_xor_sync(0xFFFFFFFF, mx0, 2));
        mx1 = fmaxf(mx1, __shfl_xor_sync(0xFFFFFFFF, mx1, 1));
        mx1 = fmaxf(mx1, __shfl_xor_sync(0xFFFFFFFF, mx1, 2));

        float mn0 = fmaxf(m0, mx0), mn1 = fmaxf(m1, mx1);
        float f0 = __expf(m0 - mn0), f1 = __expf(m1 - mn1);
        float sum0 = 0.f, sum1 = 0.f;
        #pragma unroll
        for (int j = 0; j < 8; j++) {
            s[j][0] = __expf(s[j][0] - mn0);
            s[j][1] = __expf(s[j][1] - mn0);
            s[j][2] = __expf(s[j][2] - mn1);
            s[j][3] = __expf(s[j][3] - mn1);
            sum0 += s[j][0] + s[j][1];
            sum1 += s[j][2] + s[j][3];
        }
        sum0 += __shfl_xor_sync(0xFFFFFFFF, sum0, 1);
        sum0 += __shfl_xor_sync(0xFFFFFFFF, sum0, 2);
        sum1 += __shfl_xor_sync(0xFFFFFFFF, sum1, 1);
        sum1 += __shfl_xor_sync(0xFFFFFFFF, sum1, 2);
        l0 = l0 * f0 + sum0; m0 = mn0;
        l1 = l1 * f1 + sum1; m1 = mn1;

        #pragma unroll
        for (int nf = 0; nf < 16; nf++) {
            o[nf][0] *= f0; o[nf][1] *= f0;
            o[nf][2] *= f1; o[nf][3] *= f1;
        }

        #pragma unroll
        for (int kk = 0; kk < 4; kk++) {
            uint32_t ph[4], pl[4];
            split2(s[2 * kk][0],     s[2 * kk][1],     ph[0], pl[0]);
            split2(s[2 * kk][2],     s[2 * kk][3],     ph[1], pl[1]);
            split2(s[2 * kk + 1][0], s[2 * kk + 1][1], ph[2], pl[2]);
            split2(s[2 * kk + 1][2], s[2 * kk + 1][3], ph[3], pl[3]);
            #pragma unroll
            for (int j = 0; j < 8; j++) {
                uint32_t vh[4], vl[4];
                ldsm4t(vh, sptr(&sm->V[0][kk * 16 + (lane & 15)][j * 16 + (lane >> 4) * 8]));
                ldsm4t(vl, sptr(&sm->V[1][kk * 16 + (lane & 15)][j * 16 + (lane >> 4) * 8]));
                mma16816(o[2 * j],     ph, &vh[0]);
                mma16816(o[2 * j],     pl, &vh[0]);
                mma16816(o[2 * j],     ph, &vl[0]);
                mma16816(o[2 * j + 1], ph, &vh[2]);
                mma16816(o[2 * j + 1], pl, &vh[2]);
                mma16816(o[2 * j + 1], ph, &vl[2]);
            }
        }
    }

    float il0 = 1.f / l0, il1 = 1.f / l1;
    #pragma unroll
    for (int nf = 0; nf < 16; nf++) {
        int col = nf * 8 + cc;
        uint32_t h, l;
        split2(o[nf][0] * il0, o[nf][1] * il0, h, l);
        *reinterpret_cast<uint32_t*>(&Ah[qoff + (size_t)row0 * QDIM + col]) = h;
        *reinterpret_cast<uint32_t*>(&Al[qoff + (size_t)row0 * QDIM + col]) = l;
        split2(o[nf][2] * il1, o[nf][3] * il1, h, l);
        *reinterpret_cast<uint32_t*>(&Ah[qoff + (size_t)row1 * QDIM + col]) = h;
        *reinterpret_cast<uint32_t*>(&Al[qoff + (size_t)row1 * QDIM + col]) = l;
    }
}

// ---------------------------------------------------------------------------
// Launch
// ---------------------------------------------------------------------------
extern "C" void kernel_launch(void* const* d_in, const int* in_sizes, int n_in,
                              void* d_out, int out_size)
{
    const float* x   = (const float*)d_in[0];
    const float* wq  = (const float*)d_in[1];
    const float* bq  = (const float*)d_in[2];
    const float* wkv = (const float*)d_in[3];
    const float* bkv = (const float*)d_in[4];
    const float* wo  = (const float*)d_in[5];
    float* out = (float*)d_out;

    void *pxh, *pxl, *pwqh, *pwql, *pwkvh, *pwkvl, *pwoh, *pwol;
    void *pqh, *pql, *pkvh, *pkvl, *pah, *pal;
    cudaGetSymbolAddress(&pxh,  g_xh);   cudaGetSymbolAddress(&pxl,  g_xl);
    cudaGetSymbolAddress(&pwqh, g_wqh);  cudaGetSymbolAddress(&pwql, g_wql);
    cudaGetSymbolAddress(&pwkvh,g_wkvh); cudaGetSymbolAddress(&pwkvl,g_wkvl);
    cudaGetSymbolAddress(&pwoh, g_woh);  cudaGetSymbolAddress(&pwol, g_wol);
    cudaGetSymbolAddress(&pqh,  g_qh);   cudaGetSymbolAddress(&pql,  g_ql);
    cudaGetSymbolAddress(&pkvh, g_kvh);  cudaGetSymbolAddress(&pkvl, g_kvl);
    cudaGetSymbolAddress(&pah,  g_ah);   cudaGetSymbolAddress(&pal,  g_al);

    pe_init_kernel<<<(T * D + 255) / 256, 256>>>();

    {
        int n4;
        n4 = MROWS * E / 4;
        split_kernel<<<(n4 + 255) / 256, 256>>>(x, (__nv_bfloat16*)pxh, (__nv_bfloat16*)pxl, n4);
        n4 = E * QDIM / 4;
        split_kernel<<<(n4 + 255) / 256, 256>>>(wq, (__nv_bfloat16*)pwqh, (__nv_bfloat16*)pwql, n4);
        n4 = E * KVDIM / 4;
        split_kernel<<<(n4 + 255) / 256, 256>>>(wkv, (__nv_bfloat16*)pwkvh, (__nv_bfloat16*)pwkvl, n4);
        n4 = QDIM * E / 4;
        split_kernel<<<(n4 + 255) / 256, 256>>>(wo, (__nv_bfloat16*)pwoh, (__nv_bfloat16*)pwol, n4);
    }

    const size_t gsmem = sizeof(GemmSmem);
    const size_t fsmem = sizeof(FlashSmem);
    cudaFuncSetAttribute(gemm_bf16x3_kernel, cudaFuncAttributeMaxDynamicSharedMemorySize, (int)gsmem);
    cudaFuncSetAttribute(flash_mma_kernel,   cudaFuncAttributeMaxDynamicSharedMemorySize, (int)fsmem);

    {   // Q projection (+bias +PE) -> q planes
        dim3 grid(QDIM / 128, MROWS / 128);
        gemm_bf16x3_kernel<<<grid, 128, gsmem>>>(
            (const __nv_bfloat16*)pxh, (const __nv_bfloat16*)pxl,
            (const __nv_bfloat16*)pwqh, (const __nv_bfloat16*)pwql,
            bq, (__nv_bfloat16*)pqh, (__nv_bfloat16*)pql, nullptr,
            MROWS, QDIM, E, 1);
    }
    {   // KV projection (+bias, +PE on K half) -> kv planes
        dim3 grid(KVDIM / 128, MROWS / 128);
        gemm_bf16x3_kernel<<<grid, 128, gsmem>>>(
            (const __nv_bfloat16*)pxh, (const __nv_bfloat16*)pxl,
            (const __nv_bfloat16*)pwkvh, (const __nv_bfloat16*)pwkvl,
            bkv, (__nv_bfloat16*)pkvh, (__nv_bfloat16*)pkvl, nullptr,
            MROWS, KVDIM, E, 2);
    }
    {   // Flash attention -> att planes
        dim3 grid(T / 64, NH, B);
        flash_mma_kernel<<<grid, 128, fsmem>>>(
            (const __nv_bfloat16*)pqh, (const __nv_bfloat16*)pql,
            (const __nv_bfloat16*)pkvh, (const __nv_bfloat16*)pkvl,
            (__nv_bfloat16*)pah, (__nv_bfloat16*)pal);
    }
    {   // Output projection -> fp32 out
        dim3 grid(E / 128, MROWS / 128);
        gemm_bf16x3_kernel<<<grid, 128, gsmem>>>(
            (const __nv_bfloat16*)pah, (const __nv_bfloat16*)pal,
            (const __nv_bfloat16*)pwoh, (const __nv_bfloat16*)pwol,
            nullptr, nullptr, nullptr, out,
            MROWS, E, QDIM, 0);
    }
}

// round 16
// speedup vs baseline: 3.4195x; 1.3333x over previous
#include <cuda_runtime.h>
#include <cuda_fp16.h>
#include <math.h>
#include <stdint.h>

#define B   2
#define T   2048
#define E   2048
#define G   4
#define QPG 4
#define D   128
#define NH  (G*QPG)
#define QDIM (NH*D)     // 2048
#define KVDIM (2*G*D)   // 1024
#define MROWS (B*T)     // 4096

// fp16 plane scratch (device globals; no allocations allowed)
__device__ __half g_xh [MROWS * E];      // x hi
__device__ __half g_xl [MROWS * E];      // x lo
__device__ __half g_wqh[E * QDIM];       // weights: single RN-fp16 plane
__device__ __half g_wkvh[E * KVDIM];
__device__ __half g_woh[QDIM * E];
__device__ __half g_qh [MROWS * QDIM];   // q hi/lo (A of QK^T)
__device__ __half g_ql [MROWS * QDIM];
__device__ __half g_kvh[MROWS * KVDIM];  // kv single plane (B operands)
__device__ __half g_ah [MROWS * QDIM];   // att hi/lo (A of O-proj)
__device__ __half g_al [MROWS * QDIM];
__device__ float g_pe[T * D];

// ---------------- helpers ----------------
__device__ __forceinline__ uint32_t sptr(const void* p) {
    return (uint32_t)__cvta_generic_to_shared(p);
}
__device__ __forceinline__ void ldsm4(uint32_t (&r)[4], uint32_t a) {
    asm volatile("ldmatrix.sync.aligned.m8n8.x4.shared.b16 {%0,%1,%2,%3}, [%4];\n"
                 : "=r"(r[0]), "=r"(r[1]), "=r"(r[2]), "=r"(r[3]) : "r"(a));
}
__device__ __forceinline__ void ldsm4t(uint32_t (&r)[4], uint32_t a) {
    asm volatile("ldmatrix.sync.aligned.m8n8.x4.trans.shared.b16 {%0,%1,%2,%3}, [%4];\n"
                 : "=r"(r[0]), "=r"(r[1]), "=r"(r[2]), "=r"(r[3]) : "r"(a));
}
__device__ __forceinline__ void mma16816(float (&c)[4], const uint32_t (&a)[4], const uint32_t* b) {
    asm volatile(
        "mma.sync.aligned.m16n8k16.row.col.f32.f16.f16.f32 "
        "{%0,%1,%2,%3}, {%4,%5,%6,%7}, {%8,%9}, {%0,%1,%2,%3};\n"
        : "+f"(c[0]), "+f"(c[1]), "+f"(c[2]), "+f"(c[3])
        : "r"(a[0]), "r"(a[1]), "r"(a[2]), "r"(a[3]), "r"(b[0]), "r"(b[1]));
}
__device__ __forceinline__ uint32_t pack2h(__half a, __half b) {
    __half2 t; t.x = a; t.y = b;
    return *reinterpret_cast<uint32_t*>(&t);
}
// exact fp32 -> fp16 hi/lo split (pair represents x to ~2^-22)
__device__ __forceinline__ void split2h(float x0, float x1, uint32_t& h, uint32_t& l) {
    __half h0 = __float2half_rn(x0), h1 = __float2half_rn(x1);
    __half l0 = __float2half_rn(x0 - __half2float(h0));
    __half l1 = __float2half_rn(x1 - __half2float(h1));
    h = pack2h(h0, h1); l = pack2h(l0, l1);
}
__device__ __forceinline__ void cp16(uint32_t dst, const void* src) {
    asm volatile("cp.async.cg.shared.global [%0], [%1], 16;\n" :: "r"(dst), "l"(src));
}
__device__ __forceinline__ void cp_commit() {
    asm volatile("cp.async.commit_group;\n" ::: "memory");
}
template <int N>
__device__ __forceinline__ void cp_wait() {
    asm volatile("cp.async.wait_group %0;\n" :: "n"(N) : "memory");
}

// ---------------- pre-pass kernels ----------------
// fp32 -> fp16 hi/lo planes (for x)
__global__ void split_kernel(const float* __restrict__ src,
                             __half* __restrict__ h, __half* __restrict__ l, int n4)
{
    int i = blockIdx.x * blockDim.x + threadIdx.x;
    if (i >= n4) return;
    float4 v = reinterpret_cast<const float4*>(src)[i];
    uint32_t h0, l0, h1, l1;
    split2h(v.x, v.y, h0, l0);
    split2h(v.z, v.w, h1, l1);
    reinterpret_cast<uint2*>(h)[i] = make_uint2(h0, h1);
    reinterpret_cast<uint2*>(l)[i] = make_uint2(l0, l1);
}
// fp32 -> single fp16 plane (for weights)
__global__ void convert_kernel(const float* __restrict__ src, __half* __restrict__ h, int n4)
{
    int i = blockIdx.x * blockDim.x + threadIdx.x;
    if (i >= n4) return;
    float4 v = reinterpret_cast<const float4*>(src)[i];
    uint2 o;
    o.x = pack2h(__float2half_rn(v.x), __float2half_rn(v.y));
    o.y = pack2h(__float2half_rn(v.z), __float2half_rn(v.w));
    reinterpret_cast<uint2*>(h)[i] = o;
}

__global__ void pe_init_kernel() {
    int idx = blockIdx.x * blockDim.x + threadIdx.x;
    if (idx >= T * D) return;
    int t = idx / D, d = idx % D;
    float i2  = (float)(d & ~1);
    float inv = expf(-(logf(10000.0f) * i2 / (float)D));
    float ang = (float)t * inv;
    g_pe[idx] = (d & 1) ? cosf(ang) : sinf(ang);
}

// ---------------------------------------------------------------------------
// fp16x2 tensor-core GEMM: C = (Ah+Al)[M,K] @ Wh[K,N] (+bias)(+PE)
// 128x128x32 tile, 128 threads / 4 warps (2m x 2n), 64x64 warp tile.
// cp.async double-buffered. mode 0: fp32 out  1: q planes (h+l)  2: kv plane (h)
// ---------------------------------------------------------------------------
#define ASTR 40
#define BSTR 136

struct GemmSmem {
    __half As[2][2][128][ASTR];   // [buf][plane][m][k]
    __half Bs[2][32][BSTR];       // [buf][k][n]  (hi only)
};

__global__ __launch_bounds__(128) void gemm_fp16x2_kernel(
    const __half* __restrict__ Ah, const __half* __restrict__ Al,
    const __half* __restrict__ Wh,
    const float* __restrict__ bias,
    __half* __restrict__ Ch, __half* __restrict__ Cl,
    float* __restrict__ Cf,
    int M, int N, int K, int mode)
{
    extern __shared__ char smraw[];
    GemmSmem* sm = reinterpret_cast<GemmSmem*>(smraw);

    const int tid  = threadIdx.x;
    const int lane = tid & 31;
    const int wid  = tid >> 5;
    const int wm   = wid >> 1;
    const int wn   = wid & 1;
    const int bm = blockIdx.y * 128;
    const int bn = blockIdx.x * 128;

    const int ar = tid >> 1, ac = (tid & 1) * 16;   // A: 128x32 per plane
    const int br = tid >> 3, bc = (tid & 7) * 16;   // B: 32x128

    float acc[4][8][4];
    #pragma unroll
    for (int i = 0; i < 4; i++)
        #pragma unroll
        for (int j = 0; j < 8; j++)
            #pragma unroll
            for (int e = 0; e < 4; e++) acc[i][j][e] = 0.f;

    const int NT = K / 32;

    auto load_chunk = [&](int t, int bf) {
        const int k0 = t * 32;
        #pragma unroll
        for (int h = 0; h < 2; h++) {
            int r = ar + h * 64;
            const __half* gah = &Ah[(size_t)(bm + r) * K + k0 + ac];
            const __half* gal = &Al[(size_t)(bm + r) * K + k0 + ac];
            cp16(sptr(&sm->As[bf][0][r][ac]),     gah);
            cp16(sptr(&sm->As[bf][0][r][ac + 8]), gah + 8);
            cp16(sptr(&sm->As[bf][1][r][ac]),     gal);
            cp16(sptr(&sm->As[bf][1][r][ac + 8]), gal + 8);
        }
        #pragma unroll
        for (int h = 0; h < 2; h++) {
            int r = br + h * 16;
            const __half* gwh = &Wh[(size_t)(k0 + r) * N + bn + bc];
            cp16(sptr(&sm->Bs[bf][r][bc]),     gwh);
            cp16(sptr(&sm->Bs[bf][r][bc + 8]), gwh + 8);
        }
        cp_commit();
    };

    load_chunk(0, 0);

    for (int t = 0; t < NT; t++) {
        const int buf = t & 1;
        if (t + 1 < NT) {
            load_chunk(t + 1, buf ^ 1);
            cp_wait<1>();
        } else {
            cp_wait<0>();
        }
        __syncthreads();

        #pragma unroll
        for (int ks = 0; ks < 2; ks++) {
            uint32_t af[2][4][4];   // [plane][mfrag]
            #pragma unroll
            for (int mf = 0; mf < 4; mf++) {
                ldsm4(af[0][mf], sptr(&sm->As[buf][0][wm * 64 + mf * 16 + (lane & 15)][ks * 16 + (lane >> 4) * 8]));
                ldsm4(af[1][mf], sptr(&sm->As[buf][1][wm * 64 + mf * 16 + (lane & 15)][ks * 16 + (lane >> 4) * 8]));
            }
            #pragma unroll
            for (int np = 0; np < 4; np++) {
                uint32_t bh[4];
                ldsm4t(bh, sptr(&sm->Bs[buf][ks * 16 + (lane & 15)][wn * 64 + np * 16 + (lane >> 4) * 8]));
                #pragma unroll
                for (int mf = 0; mf < 4; mf++) {
                    mma16816(acc[mf][2 * np],     af[0][mf], &bh[0]);
                    mma16816(acc[mf][2 * np],     af[1][mf], &bh[0]);
                    mma16816(acc[mf][2 * np + 1], af[0][mf], &bh[2]);
                    mma16816(acc[mf][2 * np + 1], af[1][mf], &bh[2]);
                }
            }
        }
        __syncthreads();
    }

    // epilogue: fragment c0=(r,c) c1=(r,c+1) c2=(r+8,c) c3=(r+8,c+1)
    #pragma unroll
    for (int mf = 0; mf < 4; mf++) {
        #pragma unroll
        for (int nf = 0; nf < 8; nf++) {
            int col = bn + wn * 64 + nf * 8 + (lane & 3) * 2;
            float b0 = 0.f, b1 = 0.f;
            if (mode != 0) { b0 = bias[col]; b1 = bias[col + 1]; }
            #pragma unroll
            for (int half = 0; half < 2; half++) {
                int row = bm + wm * 64 + mf * 16 + (lane >> 2) + half * 8;
                int tt  = row & (T - 1);
                float v0 = acc[mf][nf][half * 2 + 0] + b0;
                float v1 = acc[mf][nf][half * 2 + 1] + b1;
                if (mode == 0) {
                    Cf[(size_t)row * N + col]     = v0;
                    Cf[(size_t)row * N + col + 1] = v1;
                } else if (mode == 1) {
                    v0 += g_pe[tt * D + (col & (D - 1))];
                    v1 += g_pe[tt * D + ((col + 1) & (D - 1))];
                    uint32_t h, l;
                    split2h(v0, v1, h, l);
                    *reinterpret_cast<uint32_t*>(&Ch[(size_t)row * N + col]) = h;
                    *reinterpret_cast<uint32_t*>(&Cl[(size_t)row * N + col]) = l;
                } else {
                    int dc = col & (2 * D - 1);
                    if (dc < D) {
                        v0 += g_pe[tt * D + dc];
                        v1 += g_pe[tt * D + dc + 1];
                    }
                    *reinterpret_cast<uint32_t*>(&Ch[(size_t)row * N + col]) =
                        pack2h(__float2half_rn(v0), __float2half_rn(v1));
                }
            }
        }
    }
}

// ---------------------------------------------------------------------------
// Flash attention — fp16x2: Q split (hi/lo), K/V single plane, P split in regs.
// 128 threads / 4 warps, BR=BC=64, D=128. Warp w owns query rows w*16..w*16+15.
// ---------------------------------------------------------------------------
#define FSTR 136

struct FlashSmem {
    __half Q[2][64][FSTR];   // [plane][row][d]
    __half K[64][FSTR];
    __half V[64][FSTR];
};

__global__ __launch_bounds__(128) void flash_mma_kernel(
    const __half* __restrict__ Qh, const __half* __restrict__ Ql,
    const __half* __restrict__ KVh,
    __half* __restrict__ Ah, __half* __restrict__ Al)
{
    extern __shared__ char smraw[];
    FlashSmem* sm = reinterpret_cast<FlashSmem*>(smraw);

    const int tid  = threadIdx.x;
    const int lane = tid & 31;
    const int w    = tid >> 5;
    const int qb   = blockIdx.x * 64;
    const int head = blockIdx.y;
    const int b    = blockIdx.z;
    const int g    = head >> 2;

    const size_t qoff  = (size_t)b * T * QDIM  + head * D;
    const size_t kvoff = (size_t)b * T * KVDIM + g * (2 * D);

    #pragma unroll
    for (int i = 0; i < 8; i++) {
        int pos = i * 128 + tid;
        int r = pos >> 4, c = (pos & 15) * 8;
        size_t go = qoff + (size_t)(qb + r) * QDIM + c;
        *reinterpret_cast<uint4*>(&sm->Q[0][r][c]) = *reinterpret_cast<const uint4*>(&Qh[go]);
        *reinterpret_cast<uint4*>(&sm->Q[1][r][c]) = *reinterpret_cast<const uint4*>(&Ql[go]);
    }

    float o[16][4];
    #pragma unroll
    for (int nf = 0; nf < 16; nf++)
        #pragma unroll
        for (int e = 0; e < 4; e++) o[nf][e] = 0.f;

    float m0 = -INFINITY, m1 = -INFINITY, l0 = 0.f, l1 = 0.f;

    const int ntiles = qb / 64 + 1;
    const int cc   = (lane & 3) * 2;
    const int row0 = qb + w * 16 + (lane >> 2);
    const int row1 = row0 + 8;

    for (int kt = 0; kt < ntiles; kt++) {
        __syncthreads();
        #pragma unroll
        for (int i = 0; i < 8; i++) {
            int pos = i * 128 + tid;
            int r = pos >> 4, c = (pos & 15) * 8;
            size_t go = kvoff + (size_t)(kt * 64 + r) * KVDIM + c;
            *reinterpret_cast<uint4*>(&sm->K[r][c]) = *reinterpret_cast<const uint4*>(&KVh[go]);
            *reinterpret_cast<uint4*>(&sm->V[r][c]) = *reinterpret_cast<const uint4*>(&KVh[go + D]);
        }
        __syncthreads();

        // ---- QK^T (2-term: qh.kh + ql.kh) ----
        float s[8][4];
        #pragma unroll
        for (int j = 0; j < 8; j++)
            #pragma unroll
            for (int e = 0; e < 4; e++) s[j][e] = 0.f;

        #pragma unroll
        for (int ks = 0; ks < 8; ks++) {
            uint32_t qh[4], ql[4];
            ldsm4(qh, sptr(&sm->Q[0][w * 16 + (lane & 15)][ks * 16 + (lane >> 4) * 8]));
            ldsm4(ql, sptr(&sm->Q[1][w * 16 + (lane & 15)][ks * 16 + (lane >> 4) * 8]));
            #pragma unroll
            for (int j = 0; j < 4; j++) {
                uint32_t kh[4];
                ldsm4(kh, sptr(&sm->K[j * 16 + (lane & 15)][ks * 16 + (lane >> 4) * 8]));
                uint32_t b0h[2] = {kh[0], kh[2]}, b1h[2] = {kh[1], kh[3]};
                mma16816(s[2 * j],     qh, b0h);
                mma16816(s[2 * j],     ql, b0h);
                mma16816(s[2 * j + 1], qh, b1h);
                mma16816(s[2 * j + 1], ql, b1h);
            }
        }

        // ---- scale + causal mask + online softmax ----
        const float scale = 0.08838834764831845f;
        const bool maskt = (kt == ntiles - 1);
        float mx0 = -INFINITY, mx1 = -INFINITY;
        #pragma unroll
        for (int j = 0; j < 8; j++) {
            int colb = kt * 64 + j * 8 + cc;
            #pragma unroll
            for (int e = 0; e < 4; e++) {
                float v = s[j][e] * scale;
                if (maskt) {
                    int col = colb + (e & 1);
                    int rw  = (e < 2) ? row0 : row1;
                    if (col > rw) v = -INFINITY;
                }
                s[j][e] = v;
            }
            mx0 = fmaxf(mx0, fmaxf(s[j][0], s[j][1]));
            mx1 = fmaxf(mx1, fmaxf(s[j][2], s[j][3]));
        }
        mx0 = fmaxf(mx0, __shfl_xor_sync(0xFFFFFFFF, mx0, 1));
        mx0 = fmaxf(mx0, __shfl_xor_sync(0xFFFFFFFF, mx0, 2));
        mx1 = fmaxf(mx1, __shfl_xor_sync(0xFFFFFFFF, mx1, 1));
        mx1 = fmaxf(mx1, __shfl_xor_sync(0xFFFFFFFF, mx1, 2));

        float mn0 = fmaxf(m0, mx0), mn1 = fmaxf(m1, mx1);
        float f0 = __expf(m0 - mn0), f1 = __expf(m1 - mn1);
        float sum0 = 0.f, sum1 = 0.f;
        #pragma unroll
        for (int j = 0; j < 8; j++) {
            s[j][0] = __expf(s[j][0] - mn0);
            s[j][1] = __expf(s[j][1] - mn0);
            s[j][2] = __expf(s[j][2] - mn1);
            s[j][3] = __expf(s[j][3] - mn1);
            sum0 += s[j][0] + s[j][1];
            sum1 += s[j][2] + s[j][3];
        }
        sum0 += __shfl_xor_sync(0xFFFFFFFF, sum0, 1);
        sum0 += __shfl_xor_sync(0xFFFFFFFF, sum0, 2);
        sum1 += __shfl_xor_sync(0xFFFFFFFF, sum1, 1);
        sum1 += __shfl_xor_sync(0xFFFFFFFF, sum1, 2);
        l0 = l0 * f0 + sum0; m0 = mn0;
        l1 = l1 * f1 + sum1; m1 = mn1;

        #pragma unroll
        for (int nf = 0; nf < 16; nf++) {
            o[nf][0] *= f0; o[nf][1] *= f0;
            o[nf][2] *= f1; o[nf][3] *= f1;
        }

        // ---- P @ V (2-term: ph.vh + pl.vh) ----
        #pragma unroll
        for (int kk = 0; kk < 4; kk++) {
            uint32_t ph[4], pl[4];
            split2h(s[2 * kk][0],     s[2 * kk][1],     ph[0], pl[0]);
            split2h(s[2 * kk][2],     s[2 * kk][3],     ph[1], pl[1]);
            split2h(s[2 * kk + 1][0], s[2 * kk + 1][1], ph[2], pl[2]);
            split2h(s[2 * kk + 1][2], s[2 * kk + 1][3], ph[3], pl[3]);
            #pragma unroll
            for (int j = 0; j < 8; j++) {
                uint32_t vh[4];
                ldsm4t(vh, sptr(&sm->V[kk * 16 + (lane & 15)][j * 16 + (lane >> 4) * 8]));
                mma16816(o[2 * j],     ph, &vh[0]);
                mma16816(o[2 * j],     pl, &vh[0]);
                mma16816(o[2 * j + 1], ph, &vh[2]);
                mma16816(o[2 * j + 1], pl, &vh[2]);
            }
        }
    }

    // ---- epilogue: write att hi/lo planes ----
    float il0 = 1.f / l0, il1 = 1.f / l1;
    #pragma unroll
    for (int nf = 0; nf < 16; nf++) {
        int col = nf * 8 + cc;
        uint32_t h, l;
        split2h(o[nf][0] * il0, o[nf][1] * il0, h, l);
        *reinterpret_cast<uint32_t*>(&Ah[qoff + (size_t)row0 * QDIM + col]) = h;
        *reinterpret_cast<uint32_t*>(&Al[qoff + (size_t)row0 * QDIM + col]) = l;
        split2h(o[nf][2] * il1, o[nf][3] * il1, h, l);
        *reinterpret_cast<uint32_t*>(&Ah[qoff + (size_t)row1 * QDIM + col]) = h;
        *reinterpret_cast<uint32_t*>(&Al[qoff + (size_t)row1 * QDIM + col]) = l;
    }
}

// ---------------------------------------------------------------------------
// Launch
// ---------------------------------------------------------------------------
extern "C" void kernel_launch(void* const* d_in, const int* in_sizes, int n_in,
                              void* d_out, int out_size)
{
    const float* x   = (const float*)d_in[0];
    const float* wq  = (const float*)d_in[1];
    const float* bq  = (const float*)d_in[2];
    const float* wkv = (const float*)d_in[3];
    const float* bkv = (const float*)d_in[4];
    const float* wo  = (const float*)d_in[5];
    float* out = (float*)d_out;

    void *pxh, *pxl, *pwqh, *pwkvh, *pwoh;
    void *pqh, *pql, *pkvh, *pah, *pal;
    cudaGetSymbolAddress(&pxh,  g_xh);   cudaGetSymbolAddress(&pxl,  g_xl);
    cudaGetSymbolAddress(&pwqh, g_wqh);
    cudaGetSymbolAddress(&pwkvh,g_wkvh);
    cudaGetSymbolAddress(&pwoh, g_woh);
    cudaGetSymbolAddress(&pqh,  g_qh);   cudaGetSymbolAddress(&pql,  g_ql);
    cudaGetSymbolAddress(&pkvh, g_kvh);
    cudaGetSymbolAddress(&pah,  g_ah);   cudaGetSymbolAddress(&pal,  g_al);

    pe_init_kernel<<<(T * D + 255) / 256, 256>>>();

    {
        int n4;
        n4 = MROWS * E / 4;
        split_kernel<<<(n4 + 255) / 256, 256>>>(x, (__half*)pxh, (__half*)pxl, n4);
        n4 = E * QDIM / 4;
        convert_kernel<<<(n4 + 255) / 256, 256>>>(wq, (__half*)pwqh, n4);
        n4 = E * KVDIM / 4;
        convert_kernel<<<(n4 + 255) / 256, 256>>>(wkv, (__half*)pwkvh, n4);
        n4 = QDIM * E / 4;
        convert_kernel<<<(n4 + 255) / 256, 256>>>(wo, (__half*)pwoh, n4);
    }

    const size_t gsmem = sizeof(GemmSmem);
    const size_t fsmem = sizeof(FlashSmem);
    cudaFuncSetAttribute(gemm_fp16x2_kernel, cudaFuncAttributeMaxDynamicSharedMemorySize, (int)gsmem);
    cudaFuncSetAttribute(flash_mma_kernel,   cudaFuncAttributeMaxDynamicSharedMemorySize, (int)fsmem);

    {   // Q projection (+bias +PE) -> q hi/lo planes
        dim3 grid(QDIM / 128, MROWS / 128);
        gemm_fp16x2_kernel<<<grid, 128, gsmem>>>(
            (const __half*)pxh, (const __half*)pxl, (const __half*)pwqh,
            bq, (__half*)pqh, (__half*)pql, nullptr,
            MROWS, QDIM, E, 1);
    }
    {   // KV projection (+bias, +PE on K half) -> kv single plane
        dim3 grid(KVDIM / 128, MROWS / 128);
        gemm_fp16x2_kernel<<<grid, 128, gsmem>>>(
            (const __half*)pxh, (const __half*)pxl, (const __half*)pwkvh,
            bkv, (__half*)pkvh, nullptr, nullptr,
            MROWS, KVDIM, E, 2);
    }
    {   // Flash attention -> att hi/lo planes
        dim3 grid(T / 64, NH, B);
        flash_mma_kernel<<<grid, 128, fsmem>>>(
            (const __half*)pqh, (const __half*)pql, (const __half*)pkvh,
            (__half*)pah, (__half*)pal);
    }
    {   // Output projection -> fp32 out
        dim3 grid(E / 128, MROWS / 128);
        gemm_fp16x2_kernel<<<grid, 128, gsmem>>>(
            (const __half*)pah, (const __half*)pal, (const __half*)pwoh,
            nullptr, nullptr, nullptr, out,
            MROWS, E, QDIM, 0);
    }
}